// round 1
// baseline (speedup 1.0000x reference)
#include <cuda_runtime.h>
#include <math.h>

#define BB 2048
#define LL 96
#define DD 256
#define EE 131072
#define GG 768   /* 3*DD */

// ---------------- static scratch (zero-initialized at module load) ----------
__device__ float g_seq[(size_t)BB * LL * DD];   // [b*LL+l][DD], padding rows stay 0
__device__ float g_xp [(size_t)LL * BB * GG];   // time-major: [l][b][GG]
__device__ float g_h1[2][BB * DD];
__device__ float g_h2[2][BB * DD];
__device__ float g_acc[BB * DD];
__device__ int   g_gather[BB * LL];
__device__ int   g_counts[BB];
__device__ int   g_offsets[BB];

// ---------------- init ------------------------------------------------------
__global__ void k_zero() {
    int i = blockIdx.x * blockDim.x + threadIdx.x;
    if (i < BB * DD) { g_h1[0][i] = 0.f; g_h2[0][i] = 0.f; g_acc[i] = 0.f; }
    if (i < BB) g_counts[i] = 0;
}

__global__ void k_hist(const int* __restrict__ idx) {
    int e = blockIdx.x * blockDim.x + threadIdx.x;
    if (e < EE) atomicAdd(&g_counts[idx[e]], 1);
}

__global__ void k_scan() {
    __shared__ int s[2][BB];
    int t = threadIdx.x;
    for (int i = t; i < BB; i += 1024) s[0][i] = g_counts[i];
    __syncthreads();
    int src = 0;
    for (int off = 1; off < BB; off <<= 1) {
        int dst = src ^ 1;
        for (int i = t; i < BB; i += 1024)
            s[dst][i] = s[src][i] + ((i >= off) ? s[src][i - off] : 0);
        __syncthreads();
        src = dst;
    }
    for (int i = t; i < BB; i += 1024) g_offsets[i] = s[src][i] - g_counts[i];
}

// One block per group: stable-sort semantics matching jnp.argsort over
// [t_0..t_{c-1}, 0 x pad]. Real element i -> slot = rank_real + (t_i>0 ? pad : 0).
__global__ void k_sort(const float* __restrict__ ts) {
    int b = blockIdx.x;
    __shared__ float st[LL];
    int cnt = g_counts[b], off = g_offsets[b];
    int t = threadIdx.x;
    for (int l = t; l < LL; l += 128) g_gather[b * LL + l] = -1;
    if (t < cnt) st[t] = ts[off + t];
    __syncthreads();
    if (t < cnt) {
        float ti = st[t];
        int rank = 0;
        for (int j = 0; j < cnt; j++) {
            float tj = st[j];
            rank += (tj < ti) || (tj == ti && j < t);
        }
        int slot = rank + (ti > 0.f ? (LL - cnt) : 0);
        g_gather[b * LL + slot] = off + t;
    }
}

// 4 rows per block, 64 threads per row (float4 copy). Padding rows untouched (stay 0).
__global__ void k_scatter(const float* __restrict__ x) {
    int row = blockIdx.x * 4 + (threadIdx.x >> 6);
    int c = threadIdx.x & 63;
    int src = g_gather[row];
    if (src < 0) return;
    reinterpret_cast<float4*>(g_seq + (size_t)row * DD)[c] =
        reinterpret_cast<const float4*>(x + (size_t)src * DD)[c];
}

// ---------------- input GEMM: xp = seq @ Wih0^T + bih0 ----------------------
// M=BB*LL, N=768, K=256. 128x128 tile, 8x8 microtile, Kc=16.
__global__ void __launch_bounds__(256) k_ingemm(const float* __restrict__ wih,
                                                const float* __restrict__ bih) {
    __shared__ __align__(16) float As[16][136];
    __shared__ __align__(16) float Bs[16][136];
    int m0 = blockIdx.x * 128, n0 = blockIdx.y * 128;
    int tid = threadIdx.x;
    int tm = tid & 15, tn = tid >> 4;
    float acc[8][8] = {};
    for (int kk = 0; kk < DD; kk += 16) {
#pragma unroll
        for (int v = 0; v < 2; v++) {
            int idx = tid + v * 256;            // 0..511
            int row = idx >> 2, c4 = (idx & 3) * 4;
            float4 a = *(const float4*)&g_seq[(size_t)(m0 + row) * DD + kk + c4];
            As[c4 + 0][row] = a.x; As[c4 + 1][row] = a.y;
            As[c4 + 2][row] = a.z; As[c4 + 3][row] = a.w;
            float4 b = *(const float4*)&wih[(size_t)(n0 + row) * DD + kk + c4];
            Bs[c4 + 0][row] = b.x; Bs[c4 + 1][row] = b.y;
            Bs[c4 + 2][row] = b.z; Bs[c4 + 3][row] = b.w;
        }
        __syncthreads();
#pragma unroll
        for (int k = 0; k < 16; k++) {
            float4 a0 = *(const float4*)&As[k][tm * 8];
            float4 a1 = *(const float4*)&As[k][tm * 8 + 4];
            float4 b0 = *(const float4*)&Bs[k][tn * 8];
            float4 b1 = *(const float4*)&Bs[k][tn * 8 + 4];
            float av[8] = {a0.x, a0.y, a0.z, a0.w, a1.x, a1.y, a1.z, a1.w};
            float bv[8] = {b0.x, b0.y, b0.z, b0.w, b1.x, b1.y, b1.z, b1.w};
#pragma unroll
            for (int i = 0; i < 8; i++)
#pragma unroll
                for (int j = 0; j < 8; j++) acc[i][j] += av[i] * bv[j];
        }
        __syncthreads();
    }
#pragma unroll
    for (int i = 0; i < 8; i++) {
        int m = m0 + tm * 8 + i;
        int b = m / LL, l = m % LL;
        float* dst = &g_xp[((size_t)l * BB + b) * GG + n0];
#pragma unroll
        for (int j = 0; j < 8; j++) {
            int n = tn * 8 + j;
            dst[n] = acc[i][j] + bih[n0 + n];
        }
    }
}

// ---------------- layer-1 step: gh1 = h1 @ Whh0^T; gates; h1' ---------------
// 64x64 tile per gate (3 gates), 4x4 microtile, Kc=16. grid (32,4).
__global__ void __launch_bounds__(256) k_step1(const float* __restrict__ whh,
                                               const float* __restrict__ bhh,
                                               int t, int pp) {
    __shared__ __align__(16) float As[16][68];
    __shared__ __align__(16) float Bs[3][16][68];
    const float* __restrict__ hin = g_h1[pp];
    float* __restrict__ hout = g_h1[pp ^ 1];
    int m0 = blockIdx.x * 64, n0 = blockIdx.y * 64;
    int tid = threadIdx.x, tm = tid & 15, tn = tid >> 4;
    float ar[4][4] = {}, az[4][4] = {}, an[4][4] = {};
    for (int kk = 0; kk < DD; kk += 16) {
        {
            int row = tid >> 2, c4 = (tid & 3) * 4;
            float4 a = *(const float4*)&hin[(size_t)(m0 + row) * DD + kk + c4];
            As[c4 + 0][row] = a.x; As[c4 + 1][row] = a.y;
            As[c4 + 2][row] = a.z; As[c4 + 3][row] = a.w;
#pragma unroll
            for (int g = 0; g < 3; g++) {
                float4 b = *(const float4*)&whh[(size_t)(g * DD + n0 + row) * DD + kk + c4];
                Bs[g][c4 + 0][row] = b.x; Bs[g][c4 + 1][row] = b.y;
                Bs[g][c4 + 2][row] = b.z; Bs[g][c4 + 3][row] = b.w;
            }
        }
        __syncthreads();
#pragma unroll
        for (int k = 0; k < 16; k++) {
            float4 av4 = *(const float4*)&As[k][tm * 4];
            float4 br4 = *(const float4*)&Bs[0][k][tn * 4];
            float4 bz4 = *(const float4*)&Bs[1][k][tn * 4];
            float4 bn4 = *(const float4*)&Bs[2][k][tn * 4];
            float av[4] = {av4.x, av4.y, av4.z, av4.w};
            float br[4] = {br4.x, br4.y, br4.z, br4.w};
            float bz[4] = {bz4.x, bz4.y, bz4.z, bz4.w};
            float bn[4] = {bn4.x, bn4.y, bn4.z, bn4.w};
#pragma unroll
            for (int i = 0; i < 4; i++)
#pragma unroll
                for (int j = 0; j < 4; j++) {
                    ar[i][j] += av[i] * br[j];
                    az[i][j] += av[i] * bz[j];
                    an[i][j] += av[i] * bn[j];
                }
        }
        __syncthreads();
    }
    const float* __restrict__ xp = &g_xp[(size_t)t * BB * GG];
#pragma unroll
    for (int i = 0; i < 4; i++) {
        int m = m0 + tm * 4 + i;
#pragma unroll
        for (int j = 0; j < 4; j++) {
            int d = n0 + tn * 4 + j;
            float xr = xp[(size_t)m * GG + d];
            float xz = xp[(size_t)m * GG + DD + d];
            float xn = xp[(size_t)m * GG + 2 * DD + d];
            float hr = ar[i][j] + bhh[d];
            float hz = az[i][j] + bhh[DD + d];
            float hn = an[i][j] + bhh[2 * DD + d];
            float r = 1.f / (1.f + expf(-(xr + hr)));
            float z = 1.f / (1.f + expf(-(xz + hz)));
            float nn = tanhf(xn + r * hn);
            float ho = hin[(size_t)m * DD + d];
            hout[(size_t)m * DD + d] = (1.f - z) * nn + z * ho;
        }
    }
}

// ---------------- layer-2 step: dual-GEMM + gates + h2' + output accum ------
// r/z accumulate jointly across K (h1new via Wih1 and h2 via Whh1); n parts kept split.
__global__ void __launch_bounds__(256) k_step2(const float* __restrict__ wih,
                                               const float* __restrict__ bih,
                                               const float* __restrict__ whh,
                                               const float* __restrict__ bhh,
                                               int pp) {
    __shared__ __align__(16) float A1s[16][68];
    __shared__ __align__(16) float A2s[16][68];
    __shared__ __align__(16) float B1s[3][16][68];
    __shared__ __align__(16) float B2s[3][16][68];
    const float* __restrict__ h1 = g_h1[pp ^ 1];   // freshly written by k_step1
    const float* __restrict__ h2in = g_h2[pp];
    float* __restrict__ h2out = g_h2[pp ^ 1];
    int m0 = blockIdx.x * 64, n0 = blockIdx.y * 64;
    int tid = threadIdx.x, tm = tid & 15, tn = tid >> 4;
    float ar[4][4] = {}, az[4][4] = {}, axn[4][4] = {}, ahn[4][4] = {};
    for (int kk = 0; kk < DD; kk += 16) {
        {
            int row = tid >> 2, c4 = (tid & 3) * 4;
            float4 a1 = *(const float4*)&h1[(size_t)(m0 + row) * DD + kk + c4];
            A1s[c4 + 0][row] = a1.x; A1s[c4 + 1][row] = a1.y;
            A1s[c4 + 2][row] = a1.z; A1s[c4 + 3][row] = a1.w;
            float4 a2 = *(const float4*)&h2in[(size_t)(m0 + row) * DD + kk + c4];
            A2s[c4 + 0][row] = a2.x; A2s[c4 + 1][row] = a2.y;
            A2s[c4 + 2][row] = a2.z; A2s[c4 + 3][row] = a2.w;
#pragma unroll
            for (int g = 0; g < 3; g++) {
                float4 b1 = *(const float4*)&wih[(size_t)(g * DD + n0 + row) * DD + kk + c4];
                B1s[g][c4 + 0][row] = b1.x; B1s[g][c4 + 1][row] = b1.y;
                B1s[g][c4 + 2][row] = b1.z; B1s[g][c4 + 3][row] = b1.w;
                float4 b2 = *(const float4*)&whh[(size_t)(g * DD + n0 + row) * DD + kk + c4];
                B2s[g][c4 + 0][row] = b2.x; B2s[g][c4 + 1][row] = b2.y;
                B2s[g][c4 + 2][row] = b2.z; B2s[g][c4 + 3][row] = b2.w;
            }
        }
        __syncthreads();
#pragma unroll
        for (int k = 0; k < 16; k++) {
            float4 a1v = *(const float4*)&A1s[k][tm * 4];
            float4 a2v = *(const float4*)&A2s[k][tm * 4];
            float4 r1v = *(const float4*)&B1s[0][k][tn * 4];
            float4 z1v = *(const float4*)&B1s[1][k][tn * 4];
            float4 n1v = *(const float4*)&B1s[2][k][tn * 4];
            float4 r2v = *(const float4*)&B2s[0][k][tn * 4];
            float4 z2v = *(const float4*)&B2s[1][k][tn * 4];
            float4 n2v = *(const float4*)&B2s[2][k][tn * 4];
            float a1[4] = {a1v.x, a1v.y, a1v.z, a1v.w};
            float a2[4] = {a2v.x, a2v.y, a2v.z, a2v.w};
            float r1[4] = {r1v.x, r1v.y, r1v.z, r1v.w};
            float z1[4] = {z1v.x, z1v.y, z1v.z, z1v.w};
            float n1[4] = {n1v.x, n1v.y, n1v.z, n1v.w};
            float r2[4] = {r2v.x, r2v.y, r2v.z, r2v.w};
            float z2[4] = {z2v.x, z2v.y, z2v.z, z2v.w};
            float n2[4] = {n2v.x, n2v.y, n2v.z, n2v.w};
#pragma unroll
            for (int i = 0; i < 4; i++)
#pragma unroll
                for (int j = 0; j < 4; j++) {
                    ar[i][j] += a1[i] * r1[j];
                    ar[i][j] += a2[i] * r2[j];
                    az[i][j] += a1[i] * z1[j];
                    az[i][j] += a2[i] * z2[j];
                    axn[i][j] += a1[i] * n1[j];
                    ahn[i][j] += a2[i] * n2[j];
                }
        }
        __syncthreads();
    }
#pragma unroll
    for (int i = 0; i < 4; i++) {
        int m = m0 + tm * 4 + i;
#pragma unroll
        for (int j = 0; j < 4; j++) {
            int d = n0 + tn * 4 + j;
            float r = 1.f / (1.f + expf(-(ar[i][j] + bih[d] + bhh[d])));
            float z = 1.f / (1.f + expf(-(az[i][j] + bih[DD + d] + bhh[DD + d])));
            float nn = tanhf(axn[i][j] + bih[2 * DD + d] + r * (ahn[i][j] + bhh[2 * DD + d]));
            float ho = h2in[(size_t)m * DD + d];
            float hnew = (1.f - z) * nn + z * ho;
            h2out[(size_t)m * DD + d] = hnew;
            g_acc[(size_t)m * DD + d] += hnew;
        }
    }
}

__global__ void k_final(float* __restrict__ out) {
    int i = blockIdx.x * blockDim.x + threadIdx.x;
    if (i < BB * DD) out[i] = g_acc[i] * (1.f / (float)LL);
}

// ---------------- launch ----------------------------------------------------
extern "C" void kernel_launch(void* const* d_in, const int* in_sizes, int n_in,
                              void* d_out, int out_size) {
    const float* x    = (const float*)d_in[0];
    const float* ts   = (const float*)d_in[1];
    const float* wih0 = (const float*)d_in[2];
    const float* whh0 = (const float*)d_in[3];
    const float* bih0 = (const float*)d_in[4];
    const float* bhh0 = (const float*)d_in[5];
    const float* wih1 = (const float*)d_in[6];
    const float* whh1 = (const float*)d_in[7];
    const float* bih1 = (const float*)d_in[8];
    const float* bhh1 = (const float*)d_in[9];
    const int*   idx  = (const int*)d_in[10];

    k_zero<<<(BB * DD + 255) / 256, 256>>>();
    k_hist<<<EE / 256, 256>>>(idx);
    k_scan<<<1, 1024>>>();
    k_sort<<<BB, 128>>>(ts);
    k_scatter<<<(BB * LL) / 4, 256>>>(x);
    k_ingemm<<<dim3((BB * LL) / 128, GG / 128), 256>>>(wih0, bih0);

    int pp = 0;
    for (int t = 0; t < LL; t++) {
        k_step1<<<dim3(32, 4), 256>>>(whh0, bhh0, t, pp);
        k_step2<<<dim3(32, 4), 256>>>(wih1, bih1, whh1, bhh1, pp);
        pp ^= 1;
    }
    k_final<<<(BB * DD + 255) / 256, 256>>>((float*)d_out);
}

// round 2
// speedup vs baseline: 1.8093x; 1.8093x over previous
#include <cuda_runtime.h>
#include <cuda_fp16.h>
#include <math.h>
#include <stdint.h>

#define BB 2048
#define LL 96
#define DD 256
#define EE 131072
#define GG 768   /* 3*DD */
#define PITCH 40 /* halves per 32-half smem row (conflict-free ldmatrix) */

// ---------------- static scratch (zero-initialized at module load) ----------
__device__ __align__(128) __half g_seq16[(size_t)BB * LL * DD]; // padding rows stay 0
__device__ __align__(128) float  g_xp[(size_t)LL * BB * GG];    // time-major [l][b][768]
__device__ __align__(128) float  g_h1f[2][BB * DD];
__device__ __align__(128) float  g_h2f[2][BB * DD];
__device__ __align__(128) __half g_h1h[2][BB * DD];
__device__ __align__(128) __half g_h2h[2][BB * DD];
__device__ __align__(128) float  g_acc[BB * DD];
__device__ __align__(128) __half g_w16[4][GG * DD];  // wih0, whh0, wih1, whh1
__device__ int g_gather[BB * LL];
__device__ int g_counts[BB];
__device__ int g_offsets[BB];

// ---------------- helpers ---------------------------------------------------
__device__ __forceinline__ uint32_t sptr(const void* p) {
    return (uint32_t)__cvta_generic_to_shared(p);
}
__device__ __forceinline__ void ldsm4(uint32_t r[4], uint32_t addr) {
    asm volatile("ldmatrix.sync.aligned.m8n8.x4.shared.b16 {%0,%1,%2,%3}, [%4];"
                 : "=r"(r[0]), "=r"(r[1]), "=r"(r[2]), "=r"(r[3]) : "r"(addr));
}
__device__ __forceinline__ void mma16816(float c[4], const uint32_t a[4],
                                         uint32_t b0, uint32_t b1) {
    asm volatile(
        "mma.sync.aligned.m16n8k16.row.col.f32.f16.f16.f32 "
        "{%0,%1,%2,%3}, {%4,%5,%6,%7}, {%8,%9}, {%0,%1,%2,%3};"
        : "+f"(c[0]), "+f"(c[1]), "+f"(c[2]), "+f"(c[3])
        : "r"(a[0]), "r"(a[1]), "r"(a[2]), "r"(a[3]), "r"(b0), "r"(b1));
}
__device__ __forceinline__ float sigm(float x) { return 1.f / (1.f + expf(-x)); }

// ---------------- init ------------------------------------------------------
__global__ void k_zero() {
    int i = blockIdx.x * blockDim.x + threadIdx.x;
    if (i < BB * DD) {
        g_h1f[0][i] = 0.f; g_h2f[0][i] = 0.f; g_acc[i] = 0.f;
        g_h1h[0][i] = __float2half(0.f); g_h2h[0][i] = __float2half(0.f);
    }
    if (i < BB) g_counts[i] = 0;
}

__global__ void k_hist(const int* __restrict__ idx) {
    int e = blockIdx.x * blockDim.x + threadIdx.x;
    if (e < EE) atomicAdd(&g_counts[idx[e]], 1);
}

__global__ void k_scan() {
    __shared__ int s[2][BB];
    int t = threadIdx.x;
    for (int i = t; i < BB; i += 1024) s[0][i] = g_counts[i];
    __syncthreads();
    int src = 0;
    for (int off = 1; off < BB; off <<= 1) {
        int dst = src ^ 1;
        for (int i = t; i < BB; i += 1024)
            s[dst][i] = s[src][i] + ((i >= off) ? s[src][i - off] : 0);
        __syncthreads();
        src = dst;
    }
    for (int i = t; i < BB; i += 1024) g_offsets[i] = s[src][i] - g_counts[i];
}

// Stable-argsort semantics of [t_0..t_{c-1}, 0 x pad] per group.
__global__ void k_sort(const float* __restrict__ ts) {
    int b = blockIdx.x;
    __shared__ float st[LL];
    int cnt = g_counts[b], off = g_offsets[b];
    int t = threadIdx.x;
    for (int l = t; l < LL; l += 128) g_gather[b * LL + l] = -1;
    if (t < cnt) st[t] = ts[off + t];
    __syncthreads();
    if (t < cnt) {
        float ti = st[t];
        int rank = 0;
        for (int j = 0; j < cnt; j++) {
            float tj = st[j];
            rank += (tj < ti) || (tj == ti && j < t);
        }
        int slot = rank + (ti > 0.f ? (LL - cnt) : 0);
        g_gather[b * LL + slot] = off + t;
    }
}

// gather rows + convert to fp16
__global__ void k_scatter16(const float* __restrict__ x) {
    int row = blockIdx.x * 4 + (threadIdx.x >> 6);
    int c = threadIdx.x & 63;
    int src = g_gather[row];
    if (src < 0) return;
    float4 v = reinterpret_cast<const float4*>(x + (size_t)src * DD)[c];
    __half2* dst = reinterpret_cast<__half2*>(g_seq16 + (size_t)row * DD);
    dst[c * 2]     = __floats2half2_rn(v.x, v.y);
    dst[c * 2 + 1] = __floats2half2_rn(v.z, v.w);
}

__global__ void k_convw(const float* __restrict__ a, const float* __restrict__ b,
                        const float* __restrict__ c, const float* __restrict__ d) {
    int i = blockIdx.x * blockDim.x + threadIdx.x;  // < GG*DD
    g_w16[0][i] = __float2half_rn(a[i]);
    g_w16[1][i] = __float2half_rn(b[i]);
    g_w16[2][i] = __float2half_rn(c[i]);
    g_w16[3][i] = __float2half_rn(d[i]);
}

// ---------------- input GEMM: xp = seq16 @ Wih0^T + bih0 (tensor cores) -----
// M=196608, N=768, K=256. BM=128, BN=64. 8 warps = 2m x 4n (warp 64x16).
__global__ void __launch_bounds__(256) k_ingemm16(const float* __restrict__ bih) {
    __shared__ __align__(16) __half As[128 * PITCH];
    __shared__ __align__(16) __half Bs[64 * PITCH];
    const __half* __restrict__ wb = g_w16[0];
    int m0 = blockIdx.x * 128, n0 = blockIdx.y * 64;
    int tid = threadIdx.x, warp = tid >> 5, lane = tid & 31;
    int wm = warp >> 2, wn = warp & 3;
    float acc[4][2][4] = {};
    for (int kk = 0; kk < DD; kk += 32) {
        int row = tid >> 2, seg = tid & 3;
        int soff = row * PITCH + seg * 8;
        *(uint4*)&As[soff] = *(const uint4*)&g_seq16[(size_t)(m0 + row) * DD + kk + seg * 8];
        *(uint4*)&As[(row + 64) * PITCH + seg * 8] =
            *(const uint4*)&g_seq16[(size_t)(m0 + 64 + row) * DD + kk + seg * 8];
        *(uint4*)&Bs[soff] = *(const uint4*)&wb[(size_t)(n0 + row) * DD + kk + seg * 8];
        __syncthreads();
#pragma unroll
        for (int ks = 0; ks < 32; ks += 16) {
            uint32_t a[4][4], b[4];
#pragma unroll
            for (int mi = 0; mi < 4; mi++)
                ldsm4(a[mi], sptr(&As[(wm * 64 + mi * 16 + (lane & 15)) * PITCH + ks + ((lane >> 4) << 3)]));
            ldsm4(b, sptr(&Bs[(wn * 16 + (lane & 15)) * PITCH + ks + ((lane >> 4) << 3)]));
#pragma unroll
            for (int mi = 0; mi < 4; mi++) {
                mma16816(acc[mi][0], a[mi], b[0], b[2]);
                mma16816(acc[mi][1], a[mi], b[1], b[3]);
            }
        }
        __syncthreads();
    }
    int row = lane >> 2, colp = (lane & 3) * 2;
#pragma unroll
    for (int mi = 0; mi < 4; mi++) {
#pragma unroll
        for (int ci = 0; ci < 2; ci++) {
            int m = m0 + wm * 64 + mi * 16 + row + ci * 8;
            int b_ = m / LL, l = m % LL;
            float* dst = &g_xp[((size_t)l * BB + b_) * GG];
#pragma unroll
            for (int ni = 0; ni < 2; ni++) {
                int n = n0 + wn * 16 + ni * 8 + colp;
                float2 v;
                v.x = acc[mi][ni][ci * 2 + 0] + bih[n];
                v.y = acc[mi][ni][ci * 2 + 1] + bih[n + 1];
                *(float2*)&dst[n] = v;
            }
        }
    }
}

// ---------------- layer-1 step (tensor cores) -------------------------------
// Block: 64m x 64d x 3 gates. 8 warps = 2m x 4d (warp 32x16 per gate).
__global__ void __launch_bounds__(256) k_step1h(const float* __restrict__ bhh,
                                                int t, int pp) {
    __shared__ __align__(16) __half As[64 * PITCH];
    __shared__ __align__(16) __half Bs[3][64 * PITCH];
    const __half* __restrict__ hA = g_h1h[pp];
    const __half* __restrict__ wb = g_w16[1];
    int m0 = blockIdx.x * 64, d0 = blockIdx.y * 64;
    int tid = threadIdx.x, warp = tid >> 5, lane = tid & 31;
    int wm = warp >> 2, wd = warp & 3;
    float acc[3][2][2][4] = {};
    for (int kk = 0; kk < DD; kk += 32) {
        int row = tid >> 2, seg = tid & 3;
        int soff = row * PITCH + seg * 8;
        *(uint4*)&As[soff] = *(const uint4*)&hA[(size_t)(m0 + row) * DD + kk + seg * 8];
#pragma unroll
        for (int g = 0; g < 3; g++)
            *(uint4*)&Bs[g][soff] =
                *(const uint4*)&wb[(size_t)(g * DD + d0 + row) * DD + kk + seg * 8];
        __syncthreads();
#pragma unroll
        for (int ks = 0; ks < 32; ks += 16) {
            uint32_t a[2][4];
#pragma unroll
            for (int mi = 0; mi < 2; mi++)
                ldsm4(a[mi], sptr(&As[(wm * 32 + mi * 16 + (lane & 15)) * PITCH + ks + ((lane >> 4) << 3)]));
#pragma unroll
            for (int g = 0; g < 3; g++) {
                uint32_t b[4];
                ldsm4(b, sptr(&Bs[g][(wd * 16 + (lane & 15)) * PITCH + ks + ((lane >> 4) << 3)]));
#pragma unroll
                for (int mi = 0; mi < 2; mi++) {
                    mma16816(acc[g][mi][0], a[mi], b[0], b[2]);
                    mma16816(acc[g][mi][1], a[mi], b[1], b[3]);
                }
            }
        }
        __syncthreads();
    }
    const float* __restrict__ xp = g_xp + (size_t)t * BB * GG;
    const float* __restrict__ hfo = g_h1f[pp];
    float* __restrict__ hf = g_h1f[pp ^ 1];
    __half* __restrict__ hh = g_h1h[pp ^ 1];
    int row = lane >> 2, colp = (lane & 3) * 2;
#pragma unroll
    for (int mi = 0; mi < 2; mi++) {
#pragma unroll
        for (int ci = 0; ci < 2; ci++) {
            int m = m0 + wm * 32 + mi * 16 + row + ci * 8;
            const float* xpm = xp + (size_t)m * GG;
#pragma unroll
            for (int ni = 0; ni < 2; ni++) {
                int d = d0 + wd * 16 + ni * 8 + colp;
                float hv[2];
#pragma unroll
                for (int q = 0; q < 2; q++) {
                    int dd = d + q;
                    float r = sigm(xpm[dd] + acc[0][mi][ni][ci * 2 + q] + bhh[dd]);
                    float z = sigm(xpm[DD + dd] + acc[1][mi][ni][ci * 2 + q] + bhh[DD + dd]);
                    float nn = tanhf(xpm[2 * DD + dd] + r * (acc[2][mi][ni][ci * 2 + q] + bhh[2 * DD + dd]));
                    hv[q] = (1.f - z) * nn + z * hfo[(size_t)m * DD + dd];
                    hf[(size_t)m * DD + dd] = hv[q];
                }
                *(__half2*)&hh[(size_t)m * DD + d] = __floats2half2_rn(hv[0], hv[1]);
            }
        }
    }
}

// ---------------- layer-2 step (dual-GEMM tensor cores) ---------------------
__global__ void __launch_bounds__(256) k_step2h(const float* __restrict__ bih,
                                                const float* __restrict__ bhh,
                                                int pp) {
    __shared__ __align__(16) __half A1s[64 * PITCH];
    __shared__ __align__(16) __half A2s[64 * PITCH];
    __shared__ __align__(16) __half B1s[3][64 * PITCH];
    __shared__ __align__(16) __half B2s[3][64 * PITCH];
    const __half* __restrict__ hA1 = g_h1h[pp ^ 1];  // fresh layer-1 output
    const __half* __restrict__ hA2 = g_h2h[pp];
    const __half* __restrict__ w1 = g_w16[2];
    const __half* __restrict__ w2 = g_w16[3];
    int m0 = blockIdx.x * 64, d0 = blockIdx.y * 64;
    int tid = threadIdx.x, warp = tid >> 5, lane = tid & 31;
    int wm = warp >> 2, wd = warp & 3;
    float ar[2][2][4] = {}, az[2][2][4] = {}, axn[2][2][4] = {}, ahn[2][2][4] = {};
    for (int kk = 0; kk < DD; kk += 32) {
        int row = tid >> 2, seg = tid & 3;
        int soff = row * PITCH + seg * 8;
        int src = kk + seg * 8;
        *(uint4*)&A1s[soff] = *(const uint4*)&hA1[(size_t)(m0 + row) * DD + src];
        *(uint4*)&A2s[soff] = *(const uint4*)&hA2[(size_t)(m0 + row) * DD + src];
#pragma unroll
        for (int g = 0; g < 3; g++) {
            *(uint4*)&B1s[g][soff] = *(const uint4*)&w1[(size_t)(g * DD + d0 + row) * DD + src];
            *(uint4*)&B2s[g][soff] = *(const uint4*)&w2[(size_t)(g * DD + d0 + row) * DD + src];
        }
        __syncthreads();
#pragma unroll
        for (int ks = 0; ks < 32; ks += 16) {
            uint32_t a1[2][4], a2[2][4];
#pragma unroll
            for (int mi = 0; mi < 2; mi++) {
                uint32_t off = (wm * 32 + mi * 16 + (lane & 15)) * PITCH + ks + ((lane >> 4) << 3);
                ldsm4(a1[mi], sptr(&A1s[off]));
                ldsm4(a2[mi], sptr(&A2s[off]));
            }
            uint32_t boff = (wd * 16 + (lane & 15)) * PITCH + ks + ((lane >> 4) << 3);
            {   // r gate: A1*W1r + A2*W2r
                uint32_t b1[4], b2[4];
                ldsm4(b1, sptr(&B1s[0][boff]));
                ldsm4(b2, sptr(&B2s[0][boff]));
#pragma unroll
                for (int mi = 0; mi < 2; mi++) {
                    mma16816(ar[mi][0], a1[mi], b1[0], b1[2]);
                    mma16816(ar[mi][1], a1[mi], b1[1], b1[3]);
                    mma16816(ar[mi][0], a2[mi], b2[0], b2[2]);
                    mma16816(ar[mi][1], a2[mi], b2[1], b2[3]);
                }
            }
            {   // z gate
                uint32_t b1[4], b2[4];
                ldsm4(b1, sptr(&B1s[1][boff]));
                ldsm4(b2, sptr(&B2s[1][boff]));
#pragma unroll
                for (int mi = 0; mi < 2; mi++) {
                    mma16816(az[mi][0], a1[mi], b1[0], b1[2]);
                    mma16816(az[mi][1], a1[mi], b1[1], b1[3]);
                    mma16816(az[mi][0], a2[mi], b2[0], b2[2]);
                    mma16816(az[mi][1], a2[mi], b2[1], b2[3]);
                }
            }
            {   // n gate: keep xn (A1*W1n) and hn (A2*W2n) separate
                uint32_t b1[4], b2[4];
                ldsm4(b1, sptr(&B1s[2][boff]));
                ldsm4(b2, sptr(&B2s[2][boff]));
#pragma unroll
                for (int mi = 0; mi < 2; mi++) {
                    mma16816(axn[mi][0], a1[mi], b1[0], b1[2]);
                    mma16816(axn[mi][1], a1[mi], b1[1], b1[3]);
                    mma16816(ahn[mi][0], a2[mi], b2[0], b2[2]);
                    mma16816(ahn[mi][1], a2[mi], b2[1], b2[3]);
                }
            }
        }
        __syncthreads();
    }
    const float* __restrict__ hfo = g_h2f[pp];
    float* __restrict__ hf = g_h2f[pp ^ 1];
    __half* __restrict__ hh = g_h2h[pp ^ 1];
    int row = lane >> 2, colp = (lane & 3) * 2;
#pragma unroll
    for (int mi = 0; mi < 2; mi++) {
#pragma unroll
        for (int ci = 0; ci < 2; ci++) {
            int m = m0 + wm * 32 + mi * 16 + row + ci * 8;
#pragma unroll
            for (int ni = 0; ni < 2; ni++) {
                int d = d0 + wd * 16 + ni * 8 + colp;
                float hv[2];
#pragma unroll
                for (int q = 0; q < 2; q++) {
                    int dd = d + q;
                    float r = sigm(ar[mi][ni][ci * 2 + q] + bih[dd] + bhh[dd]);
                    float z = sigm(az[mi][ni][ci * 2 + q] + bih[DD + dd] + bhh[DD + dd]);
                    float nn = tanhf(axn[mi][ni][ci * 2 + q] + bih[2 * DD + dd] +
                                     r * (ahn[mi][ni][ci * 2 + q] + bhh[2 * DD + dd]));
                    hv[q] = (1.f - z) * nn + z * hfo[(size_t)m * DD + dd];
                    hf[(size_t)m * DD + dd] = hv[q];
                    g_acc[(size_t)m * DD + dd] += hv[q];
                }
                *(__half2*)&hh[(size_t)m * DD + d] = __floats2half2_rn(hv[0], hv[1]);
            }
        }
    }
}

__global__ void k_final(float* __restrict__ out) {
    int i = blockIdx.x * blockDim.x + threadIdx.x;
    if (i < BB * DD) out[i] = g_acc[i] * (1.f / (float)LL);
}

// ---------------- launch ----------------------------------------------------
extern "C" void kernel_launch(void* const* d_in, const int* in_sizes, int n_in,
                              void* d_out, int out_size) {
    const float* x    = (const float*)d_in[0];
    const float* ts   = (const float*)d_in[1];
    const float* wih0 = (const float*)d_in[2];
    const float* whh0 = (const float*)d_in[3];
    const float* bih0 = (const float*)d_in[4];
    const float* bhh0 = (const float*)d_in[5];
    const float* wih1 = (const float*)d_in[6];
    const float* whh1 = (const float*)d_in[7];
    const float* bih1 = (const float*)d_in[8];
    const float* bhh1 = (const float*)d_in[9];
    const int*   idx  = (const int*)d_in[10];

    k_zero<<<(BB * DD + 255) / 256, 256>>>();
    k_hist<<<EE / 256, 256>>>(idx);
    k_scan<<<1, 1024>>>();
    k_sort<<<BB, 128>>>(ts);
    k_scatter16<<<(BB * LL) / 4, 256>>>(x);
    k_convw<<<GG * DD / 256, 256>>>(wih0, whh0, wih1, whh1);
    k_ingemm16<<<dim3(BB * LL / 128, GG / 64), 256>>>(bih0);

    int pp = 0;
    for (int t = 0; t < LL; t++) {
        k_step1h<<<dim3(32, 4), 256>>>(bhh0, t, pp);
        k_step2h<<<dim3(32, 4), 256>>>(bih1, bhh1, pp);
        pp ^= 1;
    }
    k_final<<<(BB * DD + 255) / 256, 256>>>((float*)d_out);
}

// round 3
// speedup vs baseline: 3.1524x; 1.7423x over previous
#include <cuda_runtime.h>
#include <cuda_fp16.h>
#include <math.h>
#include <stdint.h>

#define BB 2048
#define LL 96
#define DD 256
#define EE 131072
#define GG 768   /* 3*DD */
#define PIT 40   /* halves per 32-half smem row (conflict-free ldmatrix) */

// ---------------- static scratch ---------------------------------------------
__device__ __align__(128) __half g_seq16[(size_t)BB * LL * DD]; // padding rows stay 0
__device__ __align__(128) float  g_xp[(size_t)LL * BB * GG];    // time-major [l][b][768]
__device__ __align__(128) __half g_h1h[2][BB * DD];
__device__ __align__(128) __half g_h2h[2][BB * DD];
__device__ __align__(128) __half g_w16[4][GG * DD];  // wih0, whh0, wih1, whh1
__device__ int g_gather[BB * LL];
__device__ int g_counts[BB];
__device__ unsigned g_barcnt;

// ---------------- helpers ----------------------------------------------------
__device__ __forceinline__ uint32_t sptr(const void* p) {
    return (uint32_t)__cvta_generic_to_shared(p);
}
__device__ __forceinline__ void ldsm4(uint32_t r[4], uint32_t addr) {
    asm volatile("ldmatrix.sync.aligned.m8n8.x4.shared.b16 {%0,%1,%2,%3}, [%4];"
                 : "=r"(r[0]), "=r"(r[1]), "=r"(r[2]), "=r"(r[3]) : "r"(addr));
}
__device__ __forceinline__ void mma16816(float c[4], const uint32_t a[4],
                                         uint32_t b0, uint32_t b1) {
    asm volatile(
        "mma.sync.aligned.m16n8k16.row.col.f32.f16.f16.f32 "
        "{%0,%1,%2,%3}, {%4,%5,%6,%7}, {%8,%9}, {%0,%1,%2,%3};"
        : "+f"(c[0]), "+f"(c[1]), "+f"(c[2]), "+f"(c[3])
        : "r"(a[0]), "r"(a[1]), "r"(a[2]), "r"(a[3]), "r"(b0), "r"(b1));
}
__device__ __forceinline__ void cpa16(void* dst, const void* src) {
    asm volatile("cp.async.cg.shared.global [%0], [%1], 16;\n"
                 :: "r"(sptr(dst)), "l"(src));
}
__device__ __forceinline__ void cpcommit() { asm volatile("cp.async.commit_group;\n"); }
template <int N> __device__ __forceinline__ void cpwait() {
    asm volatile("cp.async.wait_group %0;\n" :: "n"(N));
}
__device__ __forceinline__ float sigm(float x) { return 1.f / (1.f + __expf(-x)); }
__device__ __forceinline__ float tanhx(float x) {
    return 1.f - __fdividef(2.f, 1.f + __expf(2.f * x));
}

// ---------------- launch 1: zero state + convert weights ---------------------
__global__ void k_init(const float* __restrict__ a, const float* __restrict__ b,
                       const float* __restrict__ c, const float* __restrict__ d) {
    int i = blockIdx.x * blockDim.x + threadIdx.x;   // grid covers BB*DD = 524288
    if (i < BB * DD) {
        g_h1h[0][i] = __float2half(0.f);
        g_h2h[0][i] = __float2half(0.f);
    }
    if (i < BB) g_counts[i] = 0;
    if (i == 0) g_barcnt = 0u;
    if (i < GG * DD) {
        g_w16[0][i] = __float2half_rn(a[i]);
        g_w16[1][i] = __float2half_rn(b[i]);
        g_w16[2][i] = __float2half_rn(c[i]);
        g_w16[3][i] = __float2half_rn(d[i]);
    }
}

// ---------------- launch 2: histogram ----------------------------------------
__global__ void k_hist(const int* __restrict__ idx) {
    int e = blockIdx.x * blockDim.x + threadIdx.x;
    if (e < EE) atomicAdd(&g_counts[idx[e]], 1);
}

// ---------------- launch 3: per-group stable sort (computes own offset) ------
__global__ void k_sort(const float* __restrict__ ts) {
    int b = blockIdx.x;
    __shared__ float st[LL];
    __shared__ int red[128];
    int t = threadIdx.x;
    int partial = 0;
    for (int j = t; j < b; j += 128) partial += g_counts[j];
    red[t] = partial;
    __syncthreads();
    for (int s = 64; s > 0; s >>= 1) {
        if (t < s) red[t] += red[t + s];
        __syncthreads();
    }
    int off = red[0];
    int cnt = g_counts[b];
    for (int l = t; l < LL; l += 128) g_gather[b * LL + l] = -1;
    if (t < cnt) st[t] = ts[off + t];
    __syncthreads();
    if (t < cnt) {
        float ti = st[t];
        int rank = 0;
        for (int j = 0; j < cnt; j++) {
            float tj = st[j];
            rank += (tj < ti) || (tj == ti && j < t);
        }
        int slot = rank + (ti > 0.f ? (LL - cnt) : 0);
        g_gather[b * LL + slot] = off + t;
    }
}

// ---------------- launch 4: gather + fp16 convert -----------------------------
__global__ void k_scatter16(const float* __restrict__ x) {
    int row = blockIdx.x * 4 + (threadIdx.x >> 6);
    int c = threadIdx.x & 63;
    int src = g_gather[row];
    if (src < 0) return;
    float4 v = reinterpret_cast<const float4*>(x + (size_t)src * DD)[c];
    __half2* dst = reinterpret_cast<__half2*>(g_seq16 + (size_t)row * DD);
    dst[c * 2]     = __floats2half2_rn(v.x, v.y);
    dst[c * 2 + 1] = __floats2half2_rn(v.z, v.w);
}

// ---------------- launch 5: input GEMM xp = seq16 @ Wih0^T + bih0 -------------
__global__ void __launch_bounds__(256) k_ingemm16(const float* __restrict__ bih) {
    __shared__ __align__(16) __half As[128 * PIT];
    __shared__ __align__(16) __half Bs[64 * PIT];
    const __half* __restrict__ wb = g_w16[0];
    int m0 = blockIdx.x * 128, n0 = blockIdx.y * 64;
    int tid = threadIdx.x, warp = tid >> 5, lane = tid & 31;
    int wm = warp >> 2, wn = warp & 3;
    float acc[4][2][4] = {};
    for (int kk = 0; kk < DD; kk += 32) {
        int row = tid >> 2, seg = tid & 3;
        int soff = row * PIT + seg * 8;
        *(uint4*)&As[soff] = *(const uint4*)&g_seq16[(size_t)(m0 + row) * DD + kk + seg * 8];
        *(uint4*)&As[(row + 64) * PIT + seg * 8] =
            *(const uint4*)&g_seq16[(size_t)(m0 + 64 + row) * DD + kk + seg * 8];
        *(uint4*)&Bs[soff] = *(const uint4*)&wb[(size_t)(n0 + row) * DD + kk + seg * 8];
        __syncthreads();
#pragma unroll
        for (int ks = 0; ks < 32; ks += 16) {
            uint32_t a[4][4], b[4];
#pragma unroll
            for (int mi = 0; mi < 4; mi++)
                ldsm4(a[mi], sptr(&As[(wm * 64 + mi * 16 + (lane & 15)) * PIT + ks + ((lane >> 4) << 3)]));
            ldsm4(b, sptr(&Bs[(wn * 16 + (lane & 15)) * PIT + ks + ((lane >> 4) << 3)]));
#pragma unroll
            for (int mi = 0; mi < 4; mi++) {
                mma16816(acc[mi][0], a[mi], b[0], b[2]);
                mma16816(acc[mi][1], a[mi], b[1], b[3]);
            }
        }
        __syncthreads();
    }
    int row = lane >> 2, colp = (lane & 3) * 2;
#pragma unroll
    for (int mi = 0; mi < 4; mi++) {
#pragma unroll
        for (int ci = 0; ci < 2; ci++) {
            int m = m0 + wm * 64 + mi * 16 + row + ci * 8;
            int b_ = m / LL, l = m % LL;
            float* dst = &g_xp[((size_t)l * BB + b_) * GG];
#pragma unroll
            for (int ni = 0; ni < 2; ni++) {
                int n = n0 + wn * 16 + ni * 8 + colp;
                float2 v;
                v.x = acc[mi][ni][ci * 2 + 0] + bih[n];
                v.y = acc[mi][ni][ci * 2 + 1] + bih[n + 1];
                *(float2*)&dst[n] = v;
            }
        }
    }
}

// ---------------- launch 6: persistent recurrence kernel ----------------------
// 128 CTAs (all resident), 97 pipelined iterations, 96 grid barriers.
// iter k: job1 computes h1(k+1)=GRU1(h1(k),x(k)) [k<96];
//         job2 computes h2(k)=GRU2(h2(k-1),h1(k)) [k>=1]; both consume h1(k).
// fp32 carry state + running h2 sum live in registers (fixed tile per CTA).
#define SMT(stage, t) (sm + ((stage) * 8 + (t)) * 64 * PIT)

__device__ __forceinline__ void gridbar(unsigned want) {
    __syncthreads();
    if (threadIdx.x == 0) {
        __threadfence();
        atomicAdd(&g_barcnt, 1u);
        volatile unsigned* p = &g_barcnt;
        while (*p < want) {}
        __threadfence();
    }
    __syncthreads();
}

__global__ void __launch_bounds__(256, 1) k_persist(
    const float* __restrict__ bhh0, const float* __restrict__ bih1,
    const float* __restrict__ bhh1, float* __restrict__ out) {
    extern __shared__ __align__(16) __half sm[];
    const __half* __restrict__ w1 = g_w16[1];  // whh0
    const __half* __restrict__ wA = g_w16[2];  // wih1
    const __half* __restrict__ wB = g_w16[3];  // whh1
    int cid = blockIdx.x;
    int m0 = (cid >> 2) * 64, d0 = (cid & 3) * 64;
    int tid = threadIdx.x, warp = tid >> 5, lane = tid & 31;
    int wm = warp >> 2, wd = warp & 3;
    int row = lane >> 2, colp = (lane & 3) * 2;
    int lr = tid >> 2, ls = (tid & 3) * 8;       // cp.async row / half-offset
    float h1s[16] = {}, h2s[16] = {}, asum[16] = {};

    for (int k = 0; k <= 96; k++) {
        // ================= job1: layer-1 step (k < 96) =================
        if (k < 96) {
            const __half* __restrict__ hA = g_h1h[k & 1];
            float acc[3][2][2][4] = {};
            {   // prefetch chunk 0 -> stage 0
                cpa16(&SMT(0, 0)[lr * PIT + ls], &hA[(size_t)(m0 + lr) * DD + ls]);
#pragma unroll
                for (int g = 0; g < 3; g++)
                    cpa16(&SMT(0, 1 + g)[lr * PIT + ls],
                          &w1[(size_t)(g * DD + d0 + lr) * DD + ls]);
                cpcommit();
            }
            for (int c = 0; c < 8; c++) {
                if (c < 7) {
                    int kk = (c + 1) * 32, stg = (c + 1) & 1;
                    cpa16(&SMT(stg, 0)[lr * PIT + ls], &hA[(size_t)(m0 + lr) * DD + kk + ls]);
#pragma unroll
                    for (int g = 0; g < 3; g++)
                        cpa16(&SMT(stg, 1 + g)[lr * PIT + ls],
                              &w1[(size_t)(g * DD + d0 + lr) * DD + kk + ls]);
                    cpcommit();
                    cpwait<1>();
                } else {
                    cpwait<0>();
                }
                __syncthreads();
                int st = c & 1;
#pragma unroll
                for (int ks = 0; ks < 32; ks += 16) {
                    uint32_t a[2][4];
#pragma unroll
                    for (int mi = 0; mi < 2; mi++)
                        ldsm4(a[mi], sptr(&SMT(st, 0)[(wm * 32 + mi * 16 + (lane & 15)) * PIT + ks + ((lane >> 4) << 3)]));
#pragma unroll
                    for (int g = 0; g < 3; g++) {
                        uint32_t b[4];
                        ldsm4(b, sptr(&SMT(st, 1 + g)[(wd * 16 + (lane & 15)) * PIT + ks + ((lane >> 4) << 3)]));
#pragma unroll
                        for (int mi = 0; mi < 2; mi++) {
                            mma16816(acc[g][mi][0], a[mi], b[0], b[2]);
                            mma16816(acc[g][mi][1], a[mi], b[1], b[3]);
                        }
                    }
                }
                __syncthreads();
            }
            // epilogue: gates + fp32 reg carry; publish fp16 h1(k+1)
            const float* __restrict__ xp = g_xp + (size_t)k * BB * GG;
            __half* __restrict__ hh = g_h1h[(k + 1) & 1];
            int id = 0;
#pragma unroll
            for (int mi = 0; mi < 2; mi++)
#pragma unroll
                for (int ci = 0; ci < 2; ci++) {
                    int m = m0 + wm * 32 + mi * 16 + row + ci * 8;
                    const float* xpm = xp + (size_t)m * GG;
#pragma unroll
                    for (int ni = 0; ni < 2; ni++) {
                        int d = d0 + wd * 16 + ni * 8 + colp;
                        float hv[2];
#pragma unroll
                        for (int q = 0; q < 2; q++) {
                            int dd = d + q;
                            float r = sigm(xpm[dd] + acc[0][mi][ni][ci * 2 + q] + __ldg(&bhh0[dd]));
                            float z = sigm(xpm[DD + dd] + acc[1][mi][ni][ci * 2 + q] + __ldg(&bhh0[DD + dd]));
                            float nn = tanhx(xpm[2 * DD + dd] + r * (acc[2][mi][ni][ci * 2 + q] + __ldg(&bhh0[2 * DD + dd])));
                            hv[q] = (1.f - z) * nn + z * h1s[id];
                            h1s[id] = hv[q];
                            id++;
                        }
                        *(__half2*)&hh[(size_t)m * DD + d] = __floats2half2_rn(hv[0], hv[1]);
                    }
                }
        }

        // ================= job2: layer-2 step (k >= 1) =================
        if (k >= 1) {
            const __half* __restrict__ hA1 = g_h1h[k & 1];
            const __half* __restrict__ hA2 = g_h2h[(k - 1) & 1];
            float ar[2][2][4] = {}, az[2][2][4] = {}, axn[2][2][4] = {}, ahn[2][2][4] = {};
            {   // prefetch chunk 0 -> stage 0
                cpa16(&SMT(0, 0)[lr * PIT + ls], &hA1[(size_t)(m0 + lr) * DD + ls]);
                cpa16(&SMT(0, 1)[lr * PIT + ls], &hA2[(size_t)(m0 + lr) * DD + ls]);
#pragma unroll
                for (int g = 0; g < 3; g++) {
                    cpa16(&SMT(0, 2 + g)[lr * PIT + ls], &wA[(size_t)(g * DD + d0 + lr) * DD + ls]);
                    cpa16(&SMT(0, 5 + g)[lr * PIT + ls], &wB[(size_t)(g * DD + d0 + lr) * DD + ls]);
                }
                cpcommit();
            }
            for (int c = 0; c < 8; c++) {
                if (c < 7) {
                    int kk = (c + 1) * 32, stg = (c + 1) & 1;
                    cpa16(&SMT(stg, 0)[lr * PIT + ls], &hA1[(size_t)(m0 + lr) * DD + kk + ls]);
                    cpa16(&SMT(stg, 1)[lr * PIT + ls], &hA2[(size_t)(m0 + lr) * DD + kk + ls]);
#pragma unroll
                    for (int g = 0; g < 3; g++) {
                        cpa16(&SMT(stg, 2 + g)[lr * PIT + ls], &wA[(size_t)(g * DD + d0 + lr) * DD + kk + ls]);
                        cpa16(&SMT(stg, 5 + g)[lr * PIT + ls], &wB[(size_t)(g * DD + d0 + lr) * DD + kk + ls]);
                    }
                    cpcommit();
                    cpwait<1>();
                } else {
                    cpwait<0>();
                }
                __syncthreads();
                int st = c & 1;
#pragma unroll
                for (int ks = 0; ks < 32; ks += 16) {
                    uint32_t a1[2][4], a2[2][4];
#pragma unroll
                    for (int mi = 0; mi < 2; mi++) {
                        uint32_t off = (wm * 32 + mi * 16 + (lane & 15)) * PIT + ks + ((lane >> 4) << 3);
                        ldsm4(a1[mi], sptr(&SMT(st, 0)[off]));
                        ldsm4(a2[mi], sptr(&SMT(st, 1)[off]));
                    }
                    uint32_t boff = (wd * 16 + (lane & 15)) * PIT + ks + ((lane >> 4) << 3);
                    {
                        uint32_t b1[4], b2[4];
                        ldsm4(b1, sptr(&SMT(st, 2)[boff]));
                        ldsm4(b2, sptr(&SMT(st, 5)[boff]));
#pragma unroll
                        for (int mi = 0; mi < 2; mi++) {
                            mma16816(ar[mi][0], a1[mi], b1[0], b1[2]);
                            mma16816(ar[mi][1], a1[mi], b1[1], b1[3]);
                            mma16816(ar[mi][0], a2[mi], b2[0], b2[2]);
                            mma16816(ar[mi][1], a2[mi], b2[1], b2[3]);
                        }
                    }
                    {
                        uint32_t b1[4], b2[4];
                        ldsm4(b1, sptr(&SMT(st, 3)[boff]));
                        ldsm4(b2, sptr(&SMT(st, 6)[boff]));
#pragma unroll
                        for (int mi = 0; mi < 2; mi++) {
                            mma16816(az[mi][0], a1[mi], b1[0], b1[2]);
                            mma16816(az[mi][1], a1[mi], b1[1], b1[3]);
                            mma16816(az[mi][0], a2[mi], b2[0], b2[2]);
                            mma16816(az[mi][1], a2[mi], b2[1], b2[3]);
                        }
                    }
                    {
                        uint32_t b1[4], b2[4];
                        ldsm4(b1, sptr(&SMT(st, 4)[boff]));
                        ldsm4(b2, sptr(&SMT(st, 7)[boff]));
#pragma unroll
                        for (int mi = 0; mi < 2; mi++) {
                            mma16816(axn[mi][0], a1[mi], b1[0], b1[2]);
                            mma16816(axn[mi][1], a1[mi], b1[1], b1[3]);
                            mma16816(ahn[mi][0], a2[mi], b2[0], b2[2]);
                            mma16816(ahn[mi][1], a2[mi], b2[1], b2[3]);
                        }
                    }
                }
                __syncthreads();
            }
            // epilogue: gates + fp32 reg carry + running sum; publish fp16 h2(k)
            __half* __restrict__ hh = g_h2h[k & 1];
            int id = 0;
#pragma unroll
            for (int mi = 0; mi < 2; mi++)
#pragma unroll
                for (int ci = 0; ci < 2; ci++) {
                    int m = m0 + wm * 32 + mi * 16 + row + ci * 8;
#pragma unroll
                    for (int ni = 0; ni < 2; ni++) {
                        int d = d0 + wd * 16 + ni * 8 + colp;
                        float hv[2];
#pragma unroll
                        for (int q = 0; q < 2; q++) {
                            int dd = d + q;
                            float r = sigm(ar[mi][ni][ci * 2 + q] + __ldg(&bih1[dd]) + __ldg(&bhh1[dd]));
                            float z = sigm(az[mi][ni][ci * 2 + q] + __ldg(&bih1[DD + dd]) + __ldg(&bhh1[DD + dd]));
                            float nn = tanhx(axn[mi][ni][ci * 2 + q] + __ldg(&bih1[2 * DD + dd]) +
                                             r * (ahn[mi][ni][ci * 2 + q] + __ldg(&bhh1[2 * DD + dd])));
                            hv[q] = (1.f - z) * nn + z * h2s[id];
                            h2s[id] = hv[q];
                            asum[id] += hv[q];
                            id++;
                        }
                        *(__half2*)&hh[(size_t)m * DD + d] = __floats2half2_rn(hv[0], hv[1]);
                    }
                }
        }

        if (k < 96) gridbar(128u * (unsigned)(k + 1));
    }

    // write mean
    int id = 0;
#pragma unroll
    for (int mi = 0; mi < 2; mi++)
#pragma unroll
        for (int ci = 0; ci < 2; ci++) {
            int m = m0 + wm * 32 + mi * 16 + row + ci * 8;
#pragma unroll
            for (int ni = 0; ni < 2; ni++) {
                int d = d0 + wd * 16 + ni * 8 + colp;
                float2 v;
                v.x = asum[id] * (1.f / (float)LL);
                v.y = asum[id + 1] * (1.f / (float)LL);
                id += 2;
                *(float2*)&out[(size_t)m * DD + d] = v;
            }
        }
}

// ---------------- launch ------------------------------------------------------
extern "C" void kernel_launch(void* const* d_in, const int* in_sizes, int n_in,
                              void* d_out, int out_size) {
    const float* x    = (const float*)d_in[0];
    const float* ts   = (const float*)d_in[1];
    const float* wih0 = (const float*)d_in[2];
    const float* whh0 = (const float*)d_in[3];
    const float* bih0 = (const float*)d_in[4];
    const float* bhh0 = (const float*)d_in[5];
    const float* wih1 = (const float*)d_in[6];
    const float* whh1 = (const float*)d_in[7];
    const float* bih1 = (const float*)d_in[8];
    const float* bhh1 = (const float*)d_in[9];
    const int*   idx  = (const int*)d_in[10];

    static int smem_set = 0;
    if (!smem_set) {
        cudaFuncSetAttribute(k_persist, cudaFuncAttributeMaxDynamicSharedMemorySize,
                             2 * 8 * 64 * PIT * (int)sizeof(__half));
        smem_set = 1;
    }

    k_init<<<(BB * DD + 255) / 256, 256>>>(wih0, whh0, wih1, whh1);
    k_hist<<<EE / 256, 256>>>(idx);
    k_sort<<<BB, 128>>>(ts);
    k_scatter16<<<(BB * LL) / 4, 256>>>(x);
    k_ingemm16<<<dim3(BB * LL / 128, GG / 64), 256>>>(bih0);
    k_persist<<<128, 256, 2 * 8 * 64 * PIT * (int)sizeof(__half)>>>(
        bhh0, bih1, bhh1, (float*)d_out);
}

// round 5
// speedup vs baseline: 3.6207x; 1.1486x over previous
#include <cuda_runtime.h>
#include <cuda_fp16.h>
#include <math.h>
#include <stdint.h>

#define BB 2048
#define LL 96
#define DD 256
#define EE 131072
#define GG 768    /* 3*DD */
#define PIT 40    /* halves per 32-half A-row (conflict-free ldmatrix) */
#define PITW 264  /* halves per 256-half resident weight row */

#define WS_HALVES (9 * 32 * PITW)            /* 76032 */
#define AT_HALVES (2 * 2 * 128 * PIT)        /* 20480 */
#define SMEM_PERSIST ((WS_HALVES + AT_HALVES) * 2)  /* bytes = 193024 */

// ---------------- static scratch ---------------------------------------------
__device__ __align__(128) __half g_seq16[(size_t)BB * LL * DD]; // padding rows stay 0
__device__ __align__(128) float  g_xp[(size_t)LL * BB * GG];    // time-major [l][b][768]
__device__ __align__(128) __half g_h1h[2][BB * DD];
__device__ __align__(128) __half g_h2h[2][BB * DD];
__device__ __align__(128) __half g_w16[4][GG * DD];  // wih0, whh0, wih1, whh1
__device__ int g_gather[BB * LL];
__device__ int g_counts[BB];
__device__ unsigned g_barcnt;

// ---------------- helpers ----------------------------------------------------
__device__ __forceinline__ uint32_t sptr(const void* p) {
    return (uint32_t)__cvta_generic_to_shared(p);
}
__device__ __forceinline__ void ldsm4(uint32_t r[4], uint32_t addr) {
    asm volatile("ldmatrix.sync.aligned.m8n8.x4.shared.b16 {%0,%1,%2,%3}, [%4];"
                 : "=r"(r[0]), "=r"(r[1]), "=r"(r[2]), "=r"(r[3]) : "r"(addr));
}
__device__ __forceinline__ void mma16816(float c[4], const uint32_t a[4],
                                         uint32_t b0, uint32_t b1) {
    asm volatile(
        "mma.sync.aligned.m16n8k16.row.col.f32.f16.f16.f32 "
        "{%0,%1,%2,%3}, {%4,%5,%6,%7}, {%8,%9}, {%0,%1,%2,%3};"
        : "+f"(c[0]), "+f"(c[1]), "+f"(c[2]), "+f"(c[3])
        : "r"(a[0]), "r"(a[1]), "r"(a[2]), "r"(a[3]), "r"(b0), "r"(b1));
}
__device__ __forceinline__ void cpa16(void* dst, const void* src) {
    asm volatile("cp.async.cg.shared.global [%0], [%1], 16;\n"
                 :: "r"(sptr(dst)), "l"(src));
}
__device__ __forceinline__ void cpcommit() { asm volatile("cp.async.commit_group;\n"); }
template <int N> __device__ __forceinline__ void cpwait() {
    asm volatile("cp.async.wait_group %0;\n" :: "n"(N));
}
__device__ __forceinline__ float sigm(float x) { return 1.f / (1.f + __expf(-x)); }
__device__ __forceinline__ float tanhx(float x) {
    return 1.f - __fdividef(2.f, 1.f + __expf(2.f * x));
}

// ---------------- launch 1: zero state + convert weights ---------------------
__global__ void k_init(const float* __restrict__ a, const float* __restrict__ b,
                       const float* __restrict__ c, const float* __restrict__ d) {
    int i = blockIdx.x * blockDim.x + threadIdx.x;   // grid covers BB*DD = 524288
    if (i < BB * DD) {
        g_h1h[0][i] = __float2half(0.f);
        g_h2h[0][i] = __float2half(0.f);
    }
    if (i < BB) g_counts[i] = 0;
    if (i == 0) g_barcnt = 0u;
    if (i < GG * DD) {
        g_w16[0][i] = __float2half_rn(a[i]);
        g_w16[1][i] = __float2half_rn(b[i]);
        g_w16[2][i] = __float2half_rn(c[i]);
        g_w16[3][i] = __float2half_rn(d[i]);
    }
}

__global__ void k_hist(const int* __restrict__ idx) {
    int e = blockIdx.x * blockDim.x + threadIdx.x;
    if (e < EE) atomicAdd(&g_counts[idx[e]], 1);
}

// per-group stable sort (computes own offset)
__global__ void k_sort(const float* __restrict__ ts) {
    int b = blockIdx.x;
    __shared__ float st[LL];
    __shared__ int red[128];
    int t = threadIdx.x;
    int partial = 0;
    for (int j = t; j < b; j += 128) partial += g_counts[j];
    red[t] = partial;
    __syncthreads();
    for (int s = 64; s > 0; s >>= 1) {
        if (t < s) red[t] += red[t + s];
        __syncthreads();
    }
    int off = red[0];
    int cnt = g_counts[b];
    for (int l = t; l < LL; l += 128) g_gather[b * LL + l] = -1;
    if (t < cnt) st[t] = ts[off + t];
    __syncthreads();
    if (t < cnt) {
        float ti = st[t];
        int rank = 0;
        for (int j = 0; j < cnt; j++) {
            float tj = st[j];
            rank += (tj < ti) || (tj == ti && j < t);
        }
        int slot = rank + (ti > 0.f ? (LL - cnt) : 0);
        g_gather[b * LL + slot] = off + t;
    }
}

__global__ void k_scatter16(const float* __restrict__ x) {
    int row = blockIdx.x * 4 + (threadIdx.x >> 6);
    int c = threadIdx.x & 63;
    int src = g_gather[row];
    if (src < 0) return;
    float4 v = reinterpret_cast<const float4*>(x + (size_t)src * DD)[c];
    __half2* dst = reinterpret_cast<__half2*>(g_seq16 + (size_t)row * DD);
    dst[c * 2]     = __floats2half2_rn(v.x, v.y);
    dst[c * 2 + 1] = __floats2half2_rn(v.z, v.w);
}

// ---------------- input GEMM (cp.async double-buffered) -----------------------
__global__ void __launch_bounds__(256) k_ingemm16(const float* __restrict__ bih) {
    __shared__ __align__(16) __half sAB[2][192 * PIT];   // A rows 0..127, B rows 128..191
    const __half* __restrict__ wb = g_w16[0];
    int m0 = blockIdx.x * 128, n0 = blockIdx.y * 64;
    int tid = threadIdx.x, warp = tid >> 5, lane = tid & 31;
    int wm = warp >> 2, wn = warp & 3;
    float acc[4][2][4] = {};

    auto prefetch = [&](int c, int stg) {
        int kk = c * 32;
#pragma unroll
        for (int j = 0; j < 3; j++) {
            int idx = tid + j * 256;              // 0..767
            int row = idx >> 2, seg = idx & 3;
            const __half* src = (row < 128)
                ? &g_seq16[(size_t)(m0 + row) * DD + kk + seg * 8]
                : &wb[(size_t)(n0 + row - 128) * DD + kk + seg * 8];
            cpa16(&sAB[stg][row * PIT + seg * 8], src);
        }
        cpcommit();
    };

    prefetch(0, 0);
    for (int c = 0; c < 8; c++) {
        if (c < 7) { prefetch(c + 1, (c + 1) & 1); cpwait<1>(); }
        else cpwait<0>();
        __syncthreads();
        const __half* As = sAB[c & 1];
        const __half* Bs = As + 128 * PIT;
#pragma unroll
        for (int ks = 0; ks < 32; ks += 16) {
            uint32_t a[4][4], b[4];
#pragma unroll
            for (int mi = 0; mi < 4; mi++)
                ldsm4(a[mi], sptr(&As[(wm * 64 + mi * 16 + (lane & 15)) * PIT + ks + ((lane >> 4) << 3)]));
            ldsm4(b, sptr(&Bs[(wn * 16 + (lane & 15)) * PIT + ks + ((lane >> 4) << 3)]));
#pragma unroll
            for (int mi = 0; mi < 4; mi++) {
                mma16816(acc[mi][0], a[mi], b[0], b[2]);
                mma16816(acc[mi][1], a[mi], b[1], b[3]);
            }
        }
        __syncthreads();
    }
    int row = lane >> 2, colp = (lane & 3) * 2;
#pragma unroll
    for (int mi = 0; mi < 4; mi++) {
#pragma unroll
        for (int ci = 0; ci < 2; ci++) {
            int m = m0 + wm * 64 + mi * 16 + row + ci * 8;
            int b_ = m / LL, l = m % LL;
            float* dst = &g_xp[((size_t)l * BB + b_) * GG];
#pragma unroll
            for (int ni = 0; ni < 2; ni++) {
                int n = n0 + wn * 16 + ni * 8 + colp;
                float2 v;
                v.x = acc[mi][ni][ci * 2 + 0] + bih[n];
                v.y = acc[mi][ni][ci * 2 + 1] + bih[n + 1];
                *(float2*)&dst[n] = v;
            }
        }
    }
}

// ---------------- persistent recurrence: weights SMEM-resident ----------------
// 128 CTAs = 16 m-tiles (128 rows) x 8 d-tiles (32 cols). Weights (9 x 32x256
// fp16 slices) loaded once into smem; per-iter only h tiles stream via cp.async.
__device__ __forceinline__ void gridbar(unsigned want) {
    __syncthreads();
    if (threadIdx.x == 0) {
        __threadfence();
        atomicAdd(&g_barcnt, 1u);
        volatile unsigned* p = &g_barcnt;
        while (*p < want) {}
        __threadfence();
    }
    __syncthreads();
}

__global__ void __launch_bounds__(256, 1) k_persist(
    const float* __restrict__ bhh0, const float* __restrict__ bih1,
    const float* __restrict__ bhh1, float* __restrict__ out) {
    extern __shared__ __align__(16) __half sm[];
    __half* ws = sm;                                   // 9 x 32 x PITW
#define WSM(i) (ws + (i) * 32 * PITW)
#define ATM(stg, t) (sm + WS_HALVES + ((stg) * 2 + (t)) * 128 * PIT)
    int cid = blockIdx.x;
    int m0 = (cid >> 3) * 128, d0 = (cid & 7) * 32;
    int tid = threadIdx.x, warp = tid >> 5, lane = tid & 31;
    int wm = warp >> 1, wd = warp & 1;
    int row = lane >> 2, colp = (lane & 3) * 2;

    // -------- load resident weights: [0..2]=whh0, [3..5]=wih1, [6..8]=whh1 ----
    for (int idx = tid; idx < 9 * 32 * 32; idx += 256) {
        int mat = idx >> 10, rem = idx & 1023;
        int r = rem >> 5, c16 = rem & 31;
        const __half* src;
        if (mat < 3)      src = &g_w16[1][(size_t)(mat * DD + d0 + r) * DD + c16 * 8];
        else if (mat < 6) src = &g_w16[2][(size_t)((mat - 3) * DD + d0 + r) * DD + c16 * 8];
        else              src = &g_w16[3][(size_t)((mat - 6) * DD + d0 + r) * DD + c16 * 8];
        cpa16(&WSM(mat)[r * PITW + c16 * 8], src);
    }
    cpcommit();

    // -------- cache biases in registers (4 d-columns per thread) --------------
    float b0r[4], b0z[4], b0n[4], b1r[4], b1z[4], b1ni[4], b1nh[4];
#pragma unroll
    for (int ni = 0; ni < 2; ni++)
#pragma unroll
        for (int q = 0; q < 2; q++) {
            int j = ni * 2 + q;
            int dd = d0 + wd * 16 + ni * 8 + colp + q;
            b0r[j] = bhh0[dd]; b0z[j] = bhh0[DD + dd]; b0n[j] = bhh0[2 * DD + dd];
            b1r[j] = bih1[dd] + bhh1[dd];
            b1z[j] = bih1[DD + dd] + bhh1[DD + dd];
            b1ni[j] = bih1[2 * DD + dd]; b1nh[j] = bhh1[2 * DD + dd];
        }
    cpwait<0>();
    __syncthreads();

    int alr = tid >> 1, als = (tid & 1) * 16;   // A-chunk loader: row, half-offset
    float h1s[16] = {}, h2s[16] = {}, asum[16] = {};

    for (int k = 0; k <= 96; k++) {
        // ================= job1: h1(k+1) = GRU1(h1(k), x(k)) [k<96] ==========
        if (k < 96) {
            const __half* __restrict__ hA = g_h1h[k & 1];
            float acc[3][2][2][4] = {};
            cpa16(&ATM(0, 0)[alr * PIT + als], &hA[(size_t)(m0 + alr) * DD + als]);
            cpa16(&ATM(0, 0)[alr * PIT + als + 8], &hA[(size_t)(m0 + alr) * DD + als + 8]);
            cpcommit();
            for (int c = 0; c < 8; c++) {
                if (c < 7) {
                    int kk = (c + 1) * 32, stg = (c + 1) & 1;
                    cpa16(&ATM(stg, 0)[alr * PIT + als], &hA[(size_t)(m0 + alr) * DD + kk + als]);
                    cpa16(&ATM(stg, 0)[alr * PIT + als + 8], &hA[(size_t)(m0 + alr) * DD + kk + als + 8]);
                    cpcommit();
                    cpwait<1>();
                } else cpwait<0>();
                __syncthreads();
                const __half* As = ATM(c & 1, 0);
                int kk = c * 32;
#pragma unroll
                for (int ks = 0; ks < 32; ks += 16) {
                    uint32_t a[2][4];
#pragma unroll
                    for (int mi = 0; mi < 2; mi++)
                        ldsm4(a[mi], sptr(&As[(wm * 32 + mi * 16 + (lane & 15)) * PIT + ks + ((lane >> 4) << 3)]));
                    uint32_t bcol = kk + ks + ((lane >> 4) << 3);
#pragma unroll
                    for (int g = 0; g < 3; g++) {
                        uint32_t b[4];
                        ldsm4(b, sptr(&WSM(g)[(wd * 16 + (lane & 15)) * PITW + bcol]));
#pragma unroll
                        for (int mi = 0; mi < 2; mi++) {
                            mma16816(acc[g][mi][0], a[mi], b[0], b[2]);
                            mma16816(acc[g][mi][1], a[mi], b[1], b[3]);
                        }
                    }
                }
                __syncthreads();
            }
            const float* __restrict__ xp = g_xp + (size_t)k * BB * GG;
            __half* __restrict__ hh = g_h1h[(k + 1) & 1];
            int id = 0;
#pragma unroll
            for (int mi = 0; mi < 2; mi++)
#pragma unroll
                for (int ci = 0; ci < 2; ci++) {
                    int m = m0 + wm * 32 + mi * 16 + row + ci * 8;
                    const float* xpm = xp + (size_t)m * GG;
#pragma unroll
                    for (int ni = 0; ni < 2; ni++) {
                        int d = d0 + wd * 16 + ni * 8 + colp;
                        float hv[2];
#pragma unroll
                        for (int q = 0; q < 2; q++) {
                            int dd = d + q, j = ni * 2 + q;
                            float r = sigm(xpm[dd] + acc[0][mi][ni][ci * 2 + q] + b0r[j]);
                            float z = sigm(xpm[DD + dd] + acc[1][mi][ni][ci * 2 + q] + b0z[j]);
                            float nn = tanhx(xpm[2 * DD + dd] + r * (acc[2][mi][ni][ci * 2 + q] + b0n[j]));
                            hv[q] = (1.f - z) * nn + z * h1s[id];
                            h1s[id] = hv[q];
                            id++;
                        }
                        *(__half2*)&hh[(size_t)m * DD + d] = __floats2half2_rn(hv[0], hv[1]);
                    }
                }
        }

        // ================= job2: h2(k) = GRU2(h2(k-1), h1(k)) [k>=1] =========
        if (k >= 1) {
            const __half* __restrict__ hA1 = g_h1h[k & 1];
            const __half* __restrict__ hA2 = g_h2h[(k - 1) & 1];
            float ar[2][2][4] = {}, az[2][2][4] = {}, axn[2][2][4] = {}, ahn[2][2][4] = {};
            cpa16(&ATM(0, 0)[alr * PIT + als], &hA1[(size_t)(m0 + alr) * DD + als]);
            cpa16(&ATM(0, 0)[alr * PIT + als + 8], &hA1[(size_t)(m0 + alr) * DD + als + 8]);
            cpa16(&ATM(0, 1)[alr * PIT + als], &hA2[(size_t)(m0 + alr) * DD + als]);
            cpa16(&ATM(0, 1)[alr * PIT + als + 8], &hA2[(size_t)(m0 + alr) * DD + als + 8]);
            cpcommit();
            for (int c = 0; c < 8; c++) {
                if (c < 7) {
                    int kk = (c + 1) * 32, stg = (c + 1) & 1;
                    cpa16(&ATM(stg, 0)[alr * PIT + als], &hA1[(size_t)(m0 + alr) * DD + kk + als]);
                    cpa16(&ATM(stg, 0)[alr * PIT + als + 8], &hA1[(size_t)(m0 + alr) * DD + kk + als + 8]);
                    cpa16(&ATM(stg, 1)[alr * PIT + als], &hA2[(size_t)(m0 + alr) * DD + kk + als]);
                    cpa16(&ATM(stg, 1)[alr * PIT + als + 8], &hA2[(size_t)(m0 + alr) * DD + kk + als + 8]);
                    cpcommit();
                    cpwait<1>();
                } else cpwait<0>();
                __syncthreads();
                const __half* A1 = ATM(c & 1, 0);
                const __half* A2 = ATM(c & 1, 1);
                int kk = c * 32;
#pragma unroll
                for (int ks = 0; ks < 32; ks += 16) {
                    uint32_t a1[2][4], a2[2][4];
#pragma unroll
                    for (int mi = 0; mi < 2; mi++) {
                        uint32_t off = (wm * 32 + mi * 16 + (lane & 15)) * PIT + ks + ((lane >> 4) << 3);
                        ldsm4(a1[mi], sptr(&A1[off]));
                        ldsm4(a2[mi], sptr(&A2[off]));
                    }
                    uint32_t brow = (wd * 16 + (lane & 15)) * PITW + kk + ks + ((lane >> 4) << 3);
                    {
                        uint32_t b1[4], b2[4];
                        ldsm4(b1, sptr(&WSM(3)[brow]));
                        ldsm4(b2, sptr(&WSM(6)[brow]));
#pragma unroll
                        for (int mi = 0; mi < 2; mi++) {
                            mma16816(ar[mi][0], a1[mi], b1[0], b1[2]);
                            mma16816(ar[mi][1], a1[mi], b1[1], b1[3]);
                            mma16816(ar[mi][0], a2[mi], b2[0], b2[2]);
                            mma16816(ar[mi][1], a2[mi], b2[1], b2[3]);
                        }
                    }
                    {
                        uint32_t b1[4], b2[4];
                        ldsm4(b1, sptr(&WSM(4)[brow]));
                        ldsm4(b2, sptr(&WSM(7)[brow]));
#pragma unroll
                        for (int mi = 0; mi < 2; mi++) {
                            mma16816(az[mi][0], a1[mi], b1[0], b1[2]);
                            mma16816(az[mi][1], a1[mi], b1[1], b1[3]);
                            mma16816(az[mi][0], a2[mi], b2[0], b2[2]);
                            mma16816(az[mi][1], a2[mi], b2[1], b2[3]);
                        }
                    }
                    {
                        uint32_t b1[4], b2[4];
                        ldsm4(b1, sptr(&WSM(5)[brow]));
                        ldsm4(b2, sptr(&WSM(8)[brow]));
#pragma unroll
                        for (int mi = 0; mi < 2; mi++) {
                            mma16816(axn[mi][0], a1[mi], b1[0], b1[2]);
                            mma16816(axn[mi][1], a1[mi], b1[1], b1[3]);
                            mma16816(ahn[mi][0], a2[mi], b2[0], b2[2]);
                            mma16816(ahn[mi][1], a2[mi], b2[1], b2[3]);
                        }
                    }
                }
                __syncthreads();
            }
            __half* __restrict__ hh = g_h2h[k & 1];
            int id = 0;
#pragma unroll
            for (int mi = 0; mi < 2; mi++)
#pragma unroll
                for (int ci = 0; ci < 2; ci++) {
                    int m = m0 + wm * 32 + mi * 16 + row + ci * 8;
#pragma unroll
                    for (int ni = 0; ni < 2; ni++) {
                        int d = d0 + wd * 16 + ni * 8 + colp;
                        float hv[2];
#pragma unroll
                        for (int q = 0; q < 2; q++) {
                            int j = ni * 2 + q;
                            float r = sigm(ar[mi][ni][ci * 2 + q] + b1r[j]);
                            float z = sigm(az[mi][ni][ci * 2 + q] + b1z[j]);
                            float nn = tanhx(axn[mi][ni][ci * 2 + q] + b1ni[j] +
                                             r * (ahn[mi][ni][ci * 2 + q] + b1nh[j]));
                            hv[q] = (1.f - z) * nn + z * h2s[id];
                            h2s[id] = hv[q];
                            asum[id] += hv[q];
                            id++;
                        }
                        *(__half2*)&hh[(size_t)m * DD + d] = __floats2half2_rn(hv[0], hv[1]);
                    }
                }
        }

        if (k < 96) gridbar(128u * (unsigned)(k + 1));
    }

    // write mean
    int id = 0;
#pragma unroll
    for (int mi = 0; mi < 2; mi++)
#pragma unroll
        for (int ci = 0; ci < 2; ci++) {
            int m = m0 + wm * 32 + mi * 16 + row + ci * 8;
#pragma unroll
            for (int ni = 0; ni < 2; ni++) {
                int d = d0 + wd * 16 + ni * 8 + colp;
                float2 v;
                v.x = asum[id] * (1.f / (float)LL);
                v.y = asum[id + 1] * (1.f / (float)LL);
                id += 2;
                *(float2*)&out[(size_t)m * DD + d] = v;
            }
        }
}

// ---------------- launch ------------------------------------------------------
extern "C" void kernel_launch(void* const* d_in, const int* in_sizes, int n_in,
                              void* d_out, int out_size) {
    const float* x    = (const float*)d_in[0];
    const float* ts   = (const float*)d_in[1];
    const float* wih0 = (const float*)d_in[2];
    const float* whh0 = (const float*)d_in[3];
    const float* bih0 = (const float*)d_in[4];
    const float* bhh0 = (const float*)d_in[5];
    const float* wih1 = (const float*)d_in[6];
    const float* whh1 = (const float*)d_in[7];
    const float* bih1 = (const float*)d_in[8];
    const float* bhh1 = (const float*)d_in[9];
    const int*   idx  = (const int*)d_in[10];

    static int smem_set = 0;
    if (!smem_set) {
        cudaFuncSetAttribute(k_persist, cudaFuncAttributeMaxDynamicSharedMemorySize,
                             SMEM_PERSIST);
        smem_set = 1;
    }

    k_init<<<(BB * DD + 255) / 256, 256>>>(wih0, whh0, wih1, whh1);
    k_hist<<<EE / 256, 256>>>(idx);
    k_sort<<<BB, 128>>>(ts);
    k_scatter16<<<(BB * LL) / 4, 256>>>(x);
    k_ingemm16<<<dim3(BB * LL / 128, GG / 64), 256>>>(bih0);
    k_persist<<<128, 256, SMEM_PERSIST>>>(bhh0, bih1, bhh1, (float*)d_out);
}

// round 6
// speedup vs baseline: 6.5834x; 1.8182x over previous
#include <cuda_runtime.h>
#include <cuda_fp16.h>
#include <math.h>
#include <stdint.h>

#define BB 2048
#define LL 96
#define DD 256
#define EE 131072
#define GG 768    /* 3*DD */
#define PITW 264  /* halves per 256-half resident weight row */
#define PITA 72   /* halves per 64-half A-chunk row */

#define WS_HALVES (9 * 32 * PITW)              /* 76032 halves = 152064 B */
#define AT_HALVES (2 * 2 * 128 * PITA)         /* 36864 halves = 73728 B  */
#define BIAS_OFF  (WS_HALVES + AT_HALVES)      /* half offset of bias region */
#define SMEM_PERSIST (BIAS_OFF * 2 + 160 * 4)  /* 226432 bytes */

// ---------------- static scratch ---------------------------------------------
__device__ __align__(128) __half g_seq16[(size_t)BB * LL * DD]; // padding rows stay 0
__device__ __align__(128) __half g_xph[(size_t)LL * BB * GG];   // fp16 xp, bias-folded
__device__ __align__(128) __half g_h1h[2][BB * DD];
__device__ __align__(128) __half g_h2h[2][BB * DD];
__device__ __align__(128) __half g_w16[4][GG * DD];  // wih0, whh0, wih1, whh1
__device__ __align__(128) float  g_bias0[GG];        // bih0 (+bhh0 for r,z gates)
__device__ int g_gather[BB * LL];
__device__ int g_counts[BB];
__device__ unsigned g_barcnt;

// ---------------- helpers ----------------------------------------------------
__device__ __forceinline__ uint32_t sptr(const void* p) {
    return (uint32_t)__cvta_generic_to_shared(p);
}
__device__ __forceinline__ void ldsm4(uint32_t r[4], uint32_t addr) {
    asm volatile("ldmatrix.sync.aligned.m8n8.x4.shared.b16 {%0,%1,%2,%3}, [%4];"
                 : "=r"(r[0]), "=r"(r[1]), "=r"(r[2]), "=r"(r[3]) : "r"(addr));
}
__device__ __forceinline__ void mma16816(float c[4], const uint32_t a[4],
                                         uint32_t b0, uint32_t b1) {
    asm volatile(
        "mma.sync.aligned.m16n8k16.row.col.f32.f16.f16.f32 "
        "{%0,%1,%2,%3}, {%4,%5,%6,%7}, {%8,%9}, {%0,%1,%2,%3};"
        : "+f"(c[0]), "+f"(c[1]), "+f"(c[2]), "+f"(c[3])
        : "r"(a[0]), "r"(a[1]), "r"(a[2]), "r"(a[3]), "r"(b0), "r"(b1));
}
__device__ __forceinline__ void cpa16(void* dst, const void* src) {
    asm volatile("cp.async.cg.shared.global [%0], [%1], 16;\n"
                 :: "r"(sptr(dst)), "l"(src));
}
__device__ __forceinline__ void cpcommit() { asm volatile("cp.async.commit_group;\n"); }
template <int N> __device__ __forceinline__ void cpwait() {
    asm volatile("cp.async.wait_group %0;\n" :: "n"(N));
}
__device__ __forceinline__ float tanhx(float x) {
    float y;
    asm("tanh.approx.f32 %0, %1;" : "=f"(y) : "f"(x));
    return y;
}
__device__ __forceinline__ float sigm(float x) { return 0.5f * tanhx(0.5f * x) + 0.5f; }

// ---------------- launch 1: zero state + convert weights + fold bias ----------
__global__ void k_init(const float* __restrict__ a, const float* __restrict__ b,
                       const float* __restrict__ c, const float* __restrict__ d,
                       const float* __restrict__ bih0, const float* __restrict__ bhh0) {
    int i = blockIdx.x * blockDim.x + threadIdx.x;   // grid covers BB*DD = 524288
    if (i < BB * DD) {
        g_h1h[0][i] = __float2half(0.f);
        g_h2h[0][i] = __float2half(0.f);
    }
    if (i < BB) g_counts[i] = 0;
    if (i == 0) g_barcnt = 0u;
    if (i < GG) g_bias0[i] = bih0[i] + (i < 2 * DD ? bhh0[i] : 0.f);
    if (i < GG * DD) {
        g_w16[0][i] = __float2half_rn(a[i]);
        g_w16[1][i] = __float2half_rn(b[i]);
        g_w16[2][i] = __float2half_rn(c[i]);
        g_w16[3][i] = __float2half_rn(d[i]);
    }
}

__global__ void k_hist(const int* __restrict__ idx) {
    int e = blockIdx.x * blockDim.x + threadIdx.x;
    if (e < EE) atomicAdd(&g_counts[idx[e]], 1);
}

// per-group stable sort (computes own offset)
__global__ void k_sort(const float* __restrict__ ts) {
    int b = blockIdx.x;
    __shared__ float st[LL];
    __shared__ int red[128];
    int t = threadIdx.x;
    int partial = 0;
    for (int j = t; j < b; j += 128) partial += g_counts[j];
    red[t] = partial;
    __syncthreads();
    for (int s = 64; s > 0; s >>= 1) {
        if (t < s) red[t] += red[t + s];
        __syncthreads();
    }
    int off = red[0];
    int cnt = g_counts[b];
    for (int l = t; l < LL; l += 128) g_gather[b * LL + l] = -1;
    if (t < cnt) st[t] = ts[off + t];
    __syncthreads();
    if (t < cnt) {
        float ti = st[t];
        int rank = 0;
        for (int j = 0; j < cnt; j++) {
            float tj = st[j];
            rank += (tj < ti) || (tj == ti && j < t);
        }
        int slot = rank + (ti > 0.f ? (LL - cnt) : 0);
        g_gather[b * LL + slot] = off + t;
    }
}

__global__ void k_scatter16(const float* __restrict__ x) {
    int row = blockIdx.x * 4 + (threadIdx.x >> 6);
    int c = threadIdx.x & 63;
    int src = g_gather[row];
    if (src < 0) return;
    float4 v = reinterpret_cast<const float4*>(x + (size_t)src * DD)[c];
    __half2* dst = reinterpret_cast<__half2*>(g_seq16 + (size_t)row * DD);
    dst[c * 2]     = __floats2half2_rn(v.x, v.y);
    dst[c * 2 + 1] = __floats2half2_rn(v.z, v.w);
}

// ---------------- input GEMM (cp.async double-buffered, fp16 out, bias folded)
#define PITG 40
__global__ void __launch_bounds__(256) k_ingemm16() {
    __shared__ __align__(16) __half sAB[2][192 * PITG];  // A rows 0..127, B rows 128..191
    const __half* __restrict__ wb = g_w16[0];
    int m0 = blockIdx.x * 128, n0 = blockIdx.y * 64;
    int tid = threadIdx.x, warp = tid >> 5, lane = tid & 31;
    int wm = warp >> 2, wn = warp & 3;
    float acc[4][2][4] = {};

    auto prefetch = [&](int c, int stg) {
        int kk = c * 32;
#pragma unroll
        for (int j = 0; j < 3; j++) {
            int idx = tid + j * 256;              // 0..767
            int row = idx >> 2, seg = idx & 3;
            const __half* src = (row < 128)
                ? &g_seq16[(size_t)(m0 + row) * DD + kk + seg * 8]
                : &wb[(size_t)(n0 + row - 128) * DD + kk + seg * 8];
            cpa16(&sAB[stg][row * PITG + seg * 8], src);
        }
        cpcommit();
    };

    prefetch(0, 0);
    for (int c = 0; c < 8; c++) {
        if (c < 7) { prefetch(c + 1, (c + 1) & 1); cpwait<1>(); }
        else cpwait<0>();
        __syncthreads();
        const __half* As = sAB[c & 1];
        const __half* Bs = As + 128 * PITG;
#pragma unroll
        for (int ks = 0; ks < 32; ks += 16) {
            uint32_t a[4][4], b[4];
#pragma unroll
            for (int mi = 0; mi < 4; mi++)
                ldsm4(a[mi], sptr(&As[(wm * 64 + mi * 16 + (lane & 15)) * PITG + ks + ((lane >> 4) << 3)]));
            ldsm4(b, sptr(&Bs[(wn * 16 + (lane & 15)) * PITG + ks + ((lane >> 4) << 3)]));
#pragma unroll
            for (int mi = 0; mi < 4; mi++) {
                mma16816(acc[mi][0], a[mi], b[0], b[2]);
                mma16816(acc[mi][1], a[mi], b[1], b[3]);
            }
        }
        __syncthreads();
    }
    int row = lane >> 2, colp = (lane & 3) * 2;
#pragma unroll
    for (int mi = 0; mi < 4; mi++) {
#pragma unroll
        for (int ci = 0; ci < 2; ci++) {
            int m = m0 + wm * 64 + mi * 16 + row + ci * 8;
            int b_ = m / LL, l = m % LL;
            __half* dst = &g_xph[((size_t)l * BB + b_) * GG];
#pragma unroll
            for (int ni = 0; ni < 2; ni++) {
                int n = n0 + wn * 16 + ni * 8 + colp;
                *(__half2*)&dst[n] = __floats2half2_rn(
                    acc[mi][ni][ci * 2 + 0] + g_bias0[n],
                    acc[mi][ni][ci * 2 + 1] + g_bias0[n + 1]);
            }
        }
    }
}

// ---------------- persistent fused recurrence ---------------------------------
// 128 CTAs = 16 m-tiles (128 rows) x 8 d-tiles (32 cols). Per iteration ONE
// fused GEMM phase computes all 3 GEMM streams; warp w owns m rows [16w,16w+16).
__device__ __forceinline__ void gridbar(unsigned want) {
    __syncthreads();
    if (threadIdx.x == 0) {
        __threadfence();
        atomicAdd(&g_barcnt, 1u);
        volatile unsigned* p = &g_barcnt;
        while (*p < want) {}
        __threadfence();
    }
    __syncthreads();
}

__global__ void __launch_bounds__(256, 1) k_persist(
    const float* __restrict__ bhh0, const float* __restrict__ bih1,
    const float* __restrict__ bhh1, float* __restrict__ out) {
    extern __shared__ __align__(16) __half sm[];
#define WSM(i) (sm + (i) * 32 * PITW)
#define ATM(stg, t) (sm + WS_HALVES + ((stg) * 2 + (t)) * 128 * PITA)
    float* bsm = (float*)(sm + BIAS_OFF);
    int cid = blockIdx.x;
    int m0 = (cid >> 3) * 128, d0 = (cid & 7) * 32;
    int tid = threadIdx.x, warp = tid >> 5, lane = tid & 31;
    int rowq = lane >> 2, colp = (lane & 3) * 2;

    // resident weights: [0..2]=whh0, [3..5]=wih1, [6..8]=whh1
    for (int idx = tid; idx < 9 * 32 * 32; idx += 256) {
        int mat = idx >> 10, rem = idx & 1023;
        int r = rem >> 5, c16 = rem & 31;
        const __half* src;
        if (mat < 3)      src = &g_w16[1][(size_t)(mat * DD + d0 + r) * DD + c16 * 8];
        else if (mat < 6) src = &g_w16[2][(size_t)((mat - 3) * DD + d0 + r) * DD + c16 * 8];
        else              src = &g_w16[3][(size_t)((mat - 6) * DD + d0 + r) * DD + c16 * 8];
        cpa16(&WSM(mat)[r * PITW + c16 * 8], src);
    }
    cpcommit();
    // biases -> smem: [0]=bhh0_n, [32]=b1r, [64]=b1z, [96]=bih1_n, [128]=bhh1_n
    if (tid < 32) {
        int dd = d0 + tid;
        bsm[tid]       = bhh0[2 * DD + dd];
        bsm[32 + tid]  = bih1[dd] + bhh1[dd];
        bsm[64 + tid]  = bih1[DD + dd] + bhh1[DD + dd];
        bsm[96 + tid]  = bih1[2 * DD + dd];
        bsm[128 + tid] = bhh1[2 * DD + dd];
    }
    cpwait<0>();
    __syncthreads();

    int alr = tid >> 3, asg = (tid & 7) * 8;   // chunk loader: row base, half seg
    float h1s[16] = {}, h2s[16] = {}, asum[16] = {};

    for (int k = 0; k <= 96; k++) {
        const bool do1 = (k < 96), do2 = (k >= 1);
        const __half* __restrict__ hA1 = g_h1h[k & 1];
        const __half* __restrict__ hA2 = g_h2h[(k + 1) & 1];

        auto loadchunk = [&](int c, int stg) {
            int kk = c * 64;
            __half* A1 = ATM(stg, 0);
            __half* A2 = ATM(stg, 1);
#pragma unroll
            for (int j = 0; j < 4; j++) {
                int row = alr + 32 * j;
                cpa16(&A1[row * PITA + asg], &hA1[(size_t)(m0 + row) * DD + kk + asg]);
                cpa16(&A2[row * PITA + asg], &hA2[(size_t)(m0 + row) * DD + kk + asg]);
            }
            cpcommit();
        };

        loadchunk(0, 0);

        // prefetch xp tile into registers (latency hides under GEMM)
        uint32_t xpr[2][4][3];
        if (do1) {
            const __half* xph = g_xph + (size_t)k * BB * GG;
#pragma unroll
            for (int ci = 0; ci < 2; ci++)
#pragma unroll
                for (int n8 = 0; n8 < 4; n8++) {
                    int m = m0 + warp * 16 + rowq + ci * 8;
                    const __half* base = xph + (size_t)m * GG + d0 + n8 * 8 + colp;
#pragma unroll
                    for (int g = 0; g < 3; g++)
                        xpr[ci][n8][g] = __ldg((const uint32_t*)(base + g * DD));
                }
        }

        float j1a[3][4][4] = {};     // r,z,n  (h1 @ whh0)
        float j2r[4][4] = {}, j2z[4][4] = {}, j2xn[4][4] = {}, j2hn[4][4] = {};

        for (int c = 0; c < 4; c++) {
            if (c < 3) { loadchunk(c + 1, (c + 1) & 1); cpwait<1>(); }
            else cpwait<0>();
            __syncthreads();
            const __half* A1 = ATM(c & 1, 0);
            const __half* A2 = ATM(c & 1, 1);
#pragma unroll
            for (int ks = 0; ks < 4; ks++) {
                int kq = ks * 16 + ((lane >> 4) << 3);
                uint32_t a1[4], a2[4];
                ldsm4(a1, sptr(&A1[(warp * 16 + (lane & 15)) * PITA + kq]));
                if (do2) ldsm4(a2, sptr(&A2[(warp * 16 + (lane & 15)) * PITA + kq]));
                uint32_t brow = (lane & 15) * PITW + c * 64 + kq;
                if (do1) {
#pragma unroll
                    for (int g = 0; g < 3; g++)
#pragma unroll
                        for (int h = 0; h < 2; h++) {
                            uint32_t b[4];
                            ldsm4(b, sptr(&WSM(g)[brow + h * 16 * PITW]));
                            mma16816(j1a[g][h * 2 + 0], a1, b[0], b[2]);
                            mma16816(j1a[g][h * 2 + 1], a1, b[1], b[3]);
                        }
                }
                if (do2) {
#pragma unroll
                    for (int h = 0; h < 2; h++) {
                        uint32_t b[4];
                        ldsm4(b, sptr(&WSM(3)[brow + h * 16 * PITW]));
                        mma16816(j2r[h * 2 + 0], a1, b[0], b[2]);
                        mma16816(j2r[h * 2 + 1], a1, b[1], b[3]);
                        ldsm4(b, sptr(&WSM(4)[brow + h * 16 * PITW]));
                        mma16816(j2z[h * 2 + 0], a1, b[0], b[2]);
                        mma16816(j2z[h * 2 + 1], a1, b[1], b[3]);
                        ldsm4(b, sptr(&WSM(5)[brow + h * 16 * PITW]));
                        mma16816(j2xn[h * 2 + 0], a1, b[0], b[2]);
                        mma16816(j2xn[h * 2 + 1], a1, b[1], b[3]);
                        ldsm4(b, sptr(&WSM(6)[brow + h * 16 * PITW]));
                        mma16816(j2r[h * 2 + 0], a2, b[0], b[2]);
                        mma16816(j2r[h * 2 + 1], a2, b[1], b[3]);
                        ldsm4(b, sptr(&WSM(7)[brow + h * 16 * PITW]));
                        mma16816(j2z[h * 2 + 0], a2, b[0], b[2]);
                        mma16816(j2z[h * 2 + 1], a2, b[1], b[3]);
                        ldsm4(b, sptr(&WSM(8)[brow + h * 16 * PITW]));
                        mma16816(j2hn[h * 2 + 0], a2, b[0], b[2]);
                        mma16816(j2hn[h * 2 + 1], a2, b[1], b[3]);
                    }
                }
            }
            __syncthreads();
        }

        // epilogue layer 1 -> h1(k+1)
        if (do1) {
            __half* __restrict__ hh = g_h1h[(k + 1) & 1];
            int id = 0;
#pragma unroll
            for (int ci = 0; ci < 2; ci++)
#pragma unroll
                for (int n8 = 0; n8 < 4; n8++) {
                    int m = m0 + warp * 16 + rowq + ci * 8;
                    int d = d0 + n8 * 8 + colp;
                    float2 fr = __half22float2(*(__half2*)&xpr[ci][n8][0]);
                    float2 fz = __half22float2(*(__half2*)&xpr[ci][n8][1]);
                    float2 fn = __half22float2(*(__half2*)&xpr[ci][n8][2]);
                    float2 bn = *(float2*)&bsm[n8 * 8 + colp];
                    float hv[2];
#pragma unroll
                    for (int q = 0; q < 2; q++) {
                        float xr = q ? fr.y : fr.x, xz = q ? fz.y : fz.x, xn = q ? fn.y : fn.x;
                        float bnn = q ? bn.y : bn.x;
                        float r = sigm(xr + j1a[0][n8][ci * 2 + q]);
                        float z = sigm(xz + j1a[1][n8][ci * 2 + q]);
                        float nn = tanhx(xn + r * (j1a[2][n8][ci * 2 + q] + bnn));
                        hv[q] = (1.f - z) * nn + z * h1s[id];
                        h1s[id] = hv[q];
                        id++;
                    }
                    *(__half2*)&hh[(size_t)m * DD + d] = __floats2half2_rn(hv[0], hv[1]);
                }
        }

        // epilogue layer 2 -> h2, running sum
        if (do2) {
            __half* __restrict__ hh = g_h2h[k & 1];
            int id = 0;
#pragma unroll
            for (int ci = 0; ci < 2; ci++)
#pragma unroll
                for (int n8 = 0; n8 < 4; n8++) {
                    int m = m0 + warp * 16 + rowq + ci * 8;
                    int d = d0 + n8 * 8 + colp;
                    int jb = n8 * 8 + colp;
                    float2 br = *(float2*)&bsm[32 + jb];
                    float2 bz = *(float2*)&bsm[64 + jb];
                    float2 bni = *(float2*)&bsm[96 + jb];
                    float2 bnh = *(float2*)&bsm[128 + jb];
                    float hv[2];
#pragma unroll
                    for (int q = 0; q < 2; q++) {
                        float r = sigm(j2r[n8][ci * 2 + q] + (q ? br.y : br.x));
                        float z = sigm(j2z[n8][ci * 2 + q] + (q ? bz.y : bz.x));
                        float nn = tanhx(j2xn[n8][ci * 2 + q] + (q ? bni.y : bni.x) +
                                         r * (j2hn[n8][ci * 2 + q] + (q ? bnh.y : bnh.x)));
                        hv[q] = (1.f - z) * nn + z * h2s[id];
                        h2s[id] = hv[q];
                        asum[id] += hv[q];
                        id++;
                    }
                    *(__half2*)&hh[(size_t)m * DD + d] = __floats2half2_rn(hv[0], hv[1]);
                }
        }

        if (k < 96) gridbar(128u * (unsigned)(k + 1));
    }

    // write mean
    int id = 0;
#pragma unroll
    for (int ci = 0; ci < 2; ci++)
#pragma unroll
        for (int n8 = 0; n8 < 4; n8++) {
            int m = m0 + warp * 16 + rowq + ci * 8;
            int d = d0 + n8 * 8 + colp;
            float2 v;
            v.x = asum[id] * (1.f / (float)LL);
            v.y = asum[id + 1] * (1.f / (float)LL);
            id += 2;
            *(float2*)&out[(size_t)m * DD + d] = v;
        }
}

// ---------------- launch ------------------------------------------------------
extern "C" void kernel_launch(void* const* d_in, const int* in_sizes, int n_in,
                              void* d_out, int out_size) {
    const float* x    = (const float*)d_in[0];
    const float* ts   = (const float*)d_in[1];
    const float* wih0 = (const float*)d_in[2];
    const float* whh0 = (const float*)d_in[3];
    const float* bih0 = (const float*)d_in[4];
    const float* bhh0 = (const float*)d_in[5];
    const float* wih1 = (const float*)d_in[6];
    const float* whh1 = (const float*)d_in[7];
    const float* bih1 = (const float*)d_in[8];
    const float* bhh1 = (const float*)d_in[9];
    const int*   idx  = (const int*)d_in[10];

    static int smem_set = 0;
    if (!smem_set) {
        cudaFuncSetAttribute(k_persist, cudaFuncAttributeMaxDynamicSharedMemorySize,
                             SMEM_PERSIST);
        smem_set = 1;
    }

    k_init<<<(BB * DD + 255) / 256, 256>>>(wih0, whh0, wih1, whh1, bih0, bhh0);
    k_hist<<<EE / 256, 256>>>(idx);
    k_sort<<<BB, 128>>>(ts);
    k_scatter16<<<(BB * LL) / 4, 256>>>(x);
    k_ingemm16<<<dim3(BB * LL / 128, GG / 64), 256>>>();
    k_persist<<<128, 256, SMEM_PERSIST>>>(bhh0, bih1, bhh1, (float*)d_out);
}